// round 4
// baseline (speedup 1.0000x reference)
#include <cuda_runtime.h>
#include <math.h>

#define NN 100000
#define EE 1000000
#define DD 64
#define GG 128
#define SB 512
#define NB ((NN + SB - 1) / SB)

// ---------------- scratch (device globals) -----------------------------------
__device__ float g_dinv[NN];
__device__ int   g_deg[NN];
__device__ int   g_flag[NN];
__device__ float g_temb[DD];
__device__ float g_y[NN * GG];
__device__ float g_h0[NN * GG];
__device__ float g_h1[NN * (GG / 2)];
__device__ float g_h2[NN * GG];
__device__ int   g_off[NN + 1];
__device__ int   g_bsum[NB + 1];
__device__ int   g_cur[NN];
__device__ int   g_csr[EE];

// ---------------- small kernels ---------------------------------------------
__global__ void k_init(int* deg, int* flag) {
    int i = blockIdx.x * blockDim.x + threadIdx.x;
    if (i < NN) { deg[i] = 0; flag[i] = 0; }
}

__global__ void k_deg(const int* __restrict__ dst, int* deg) {
    int e = blockIdx.x * blockDim.x + threadIdx.x;
    if (e < EE) atomicAdd(&deg[dst[e]], 1);
}

__global__ void k_flags(const int* __restrict__ anm, int n_anm,
                        const int* __restrict__ nrm, int n_nrm, int* flag) {
    int i = blockIdx.x * blockDim.x + threadIdx.x;
    if (i < n_anm) atomicMax(&flag[anm[i]], 1);
    if (i < n_nrm) atomicMax(&flag[nrm[i]], 2);
}

__global__ void k_temb(const int* __restrict__ t,
                       const float* __restrict__ w1, const float* __restrict__ b1,
                       const float* __restrict__ w2, const float* __restrict__ b2,
                       float* temb) {
    __shared__ float emb[DD];
    __shared__ float h[DD];
    int j = threadIdx.x;
    float tv = (float)t[0];
    if (j < 32) {
        float freq = expf((float)j * (-logf(10000.0f) / 31.0f));
        float arg = tv * freq;
        emb[j] = sinf(arg);
        emb[j + 32] = cosf(arg);
    }
    __syncthreads();
    float acc = b1[j];
    #pragma unroll
    for (int k = 0; k < DD; k++) acc += emb[k] * w1[k * DD + j];
    acc = acc / (1.0f + expf(-acc));
    h[j] = acc;
    __syncthreads();
    float acc2 = b2[j];
    #pragma unroll
    for (int k = 0; k < DD; k++) acc2 += h[k] * w2[k * DD + j];
    temb[j] = acc2;
}

__global__ void k_dinv(const int* __restrict__ deg, float* dinv) {
    int i = blockIdx.x * blockDim.x + threadIdx.x;
    if (i < NN) dinv[i] = rsqrtf((float)deg[i] + 1.0f);
}

// ---------------- CSR build --------------------------------------------------
__global__ void k_scan1(const int* __restrict__ deg, int* off, int* bsum) {
    __shared__ int sh[SB];
    int i = blockIdx.x * SB + threadIdx.x;
    int v = (i < NN) ? deg[i] : 0;
    sh[threadIdx.x] = v;
    __syncthreads();
    for (int s = 1; s < SB; s <<= 1) {
        int t = (threadIdx.x >= s) ? sh[threadIdx.x - s] : 0;
        __syncthreads();
        sh[threadIdx.x] += t;
        __syncthreads();
    }
    if (i < NN) off[i] = sh[threadIdx.x] - v;
    if (threadIdx.x == SB - 1) bsum[blockIdx.x] = sh[SB - 1];
}

__global__ void k_scan2(int* bsum) {
    if (threadIdx.x == 0) {
        int acc = 0;
        for (int b = 0; b < NB; b++) { int t = bsum[b]; bsum[b] = acc; acc += t; }
    }
}

__global__ void k_scan3(int* off, const int* __restrict__ bsum, int* cur) {
    int i = blockIdx.x * blockDim.x + threadIdx.x;
    if (i < NN) { off[i] += bsum[i / SB]; cur[i] = 0; }
    if (i == 0) off[NN] = EE;
}

__global__ void k_fill(const int* __restrict__ src, const int* __restrict__ dst,
                       const int* __restrict__ off, int* cur, int* csr) {
    int e = blockIdx.x * blockDim.x + threadIdx.x;
    if (e < EE) {
        int d = dst[e];
        int p = off[d] + atomicAdd(&cur[d], 1);
        csr[p] = src[e];
    }
}

// ---------------- tensor-core helpers ---------------------------------------
__device__ __forceinline__ unsigned f2tf(float f) {
    unsigned r; asm("cvt.rna.tf32.f32 %0, %1;" : "=r"(r) : "f"(f)); return r;
}
__device__ __forceinline__ void mma8(float* d, const unsigned* a, unsigned b0, unsigned b1) {
    asm volatile("mma.sync.aligned.m16n8k8.row.col.f32.tf32.tf32.f32 "
        "{%0,%1,%2,%3}, {%4,%5,%6,%7}, {%8,%9}, {%0,%1,%2,%3};"
        : "+f"(d[0]), "+f"(d[1]), "+f"(d[2]), "+f"(d[3])
        : "r"(a[0]), "r"(a[1]), "r"(a[2]), "r"(a[3]), "r"(b0), "r"(b1));
}

// Build W fragments in smem: for each (kstep, jtile, lane) a uint4 {bh0,bh1,bl0,bl1}
template <int FIN, int FOUT>
__device__ __forceinline__ void build_wfrag(const float* __restrict__ Wg, unsigned* Wf, int tid) {
    for (int p = tid; p < FIN * FOUT / 2; p += 128) {
        int ks = p / ((FOUT / 8) * 32);
        int rem = p % ((FOUT / 8) * 32);
        int j = rem / 32;
        int ln = rem % 32;
        int col = j * 8 + (ln >> 2);
        int kr = ks * 8 + (ln & 3);
        float w0 = __ldg(&Wg[kr * FOUT + col]);
        float w1 = __ldg(&Wg[(kr + 4) * FOUT + col]);
        unsigned h0 = f2tf(w0), h1 = f2tf(w1);
        unsigned l0 = f2tf(w0 - __uint_as_float(h0));
        unsigned l1 = f2tf(w1 - __uint_as_float(h1));
        ((uint4*)Wf)[p] = make_uint4(h0, h1, l0, l1);
    }
}

// 3xTF32 MMA GEMM: Y[r,c] (+)= (sum_k X[r,k]*W[k,c]) * dinv[r]
// FUSE0: X is built on the fly as noise + temb + label.
template <int FIN, int FOUT, bool ACC, bool FUSE0>
__global__ void __launch_bounds__(128) k_mma(const float* __restrict__ X,
                                             const float* __restrict__ Wg,
                                             float* __restrict__ Y,
                                             const float* __restrict__ dinv,
                                             const float* __restrict__ lemb,
                                             const float* __restrict__ temb,
                                             const int* __restrict__ flag) {
    constexpr int BM = (FOUT == 128) ? 64 : 128;
    constexpr int BK = 16;
    constexpr int NJ = 8;
    constexpr int XROW = BK * 2 + 2;   // 34 words per row (hi/lo interleaved, padded)
    extern __shared__ unsigned smem_u[];
    unsigned* Wf = smem_u;                       // FIN*FOUT*2 words
    unsigned* Xs = smem_u + FIN * FOUT * 2;      // BM*XROW words
    __shared__ float temb_s[DD], l0_s[DD], l1_s[DD];

    int tid = threadIdx.x;
    int lane = tid & 31, wid = tid >> 5;
    int wx = (FOUT == 128) ? (wid & 1) : 0;
    int wy = (FOUT == 128) ? (wid >> 1) : wid;

    build_wfrag<FIN, FOUT>(Wg, Wf, tid);
    if (FUSE0 && tid < DD) {
        temb_s[tid] = temb[tid];
        l0_s[tid] = lemb[tid];
        l1_s[tid] = lemb[DD + tid];
    }

    int base = blockIdx.x * BM;
    float acc[2][NJ][4];
    #pragma unroll
    for (int mi = 0; mi < 2; mi++)
        #pragma unroll
        for (int j = 0; j < NJ; j++)
            #pragma unroll
            for (int q = 0; q < 4; q++) acc[mi][j][q] = 0.f;

    for (int kc = 0; kc < FIN; kc += BK) {
        __syncthreads();
        // stage X chunk [BM][BK] as tf32 hi/lo pairs
        for (int q = tid; q < BM * (BK / 4); q += 128) {
            int r = q / (BK / 4), kq = q % (BK / 4);
            int gr = base + r; if (gr >= NN) gr = NN - 1;
            float4 v = *(const float4*)&X[(size_t)gr * FIN + kc + kq * 4];
            float vv[4] = {v.x, v.y, v.z, v.w};
            if (FUSE0) {
                int fl = flag[gr];
                #pragma unroll
                for (int i = 0; i < 4; i++) {
                    int kk = kc + kq * 4 + i;
                    vv[i] += temb_s[kk];
                    if (fl == 1) vv[i] += l1_s[kk];
                    else if (fl == 2) vv[i] += l0_s[kk];
                }
            }
            #pragma unroll
            for (int i = 0; i < 4; i++) {
                unsigned h = f2tf(vv[i]);
                unsigned l = f2tf(vv[i] - __uint_as_float(h));
                Xs[r * XROW + (kq * 4 + i) * 2] = h;
                Xs[r * XROW + (kq * 4 + i) * 2 + 1] = l;
            }
        }
        __syncthreads();
        #pragma unroll
        for (int kl = 0; kl < BK; kl += 8) {
            int ksg = (kc + kl) >> 3;
            unsigned ah[2][4], al[2][4];
            #pragma unroll
            for (int mi = 0; mi < 2; mi++) {
                int r = wy * 32 + mi * 16 + (lane >> 2);
                int k0 = kl + (lane & 3);
                uint2 p0 = *(uint2*)&Xs[r * XROW + k0 * 2];
                uint2 p1 = *(uint2*)&Xs[(r + 8) * XROW + k0 * 2];
                uint2 p2 = *(uint2*)&Xs[r * XROW + (k0 + 4) * 2];
                uint2 p3 = *(uint2*)&Xs[(r + 8) * XROW + (k0 + 4) * 2];
                ah[mi][0] = p0.x; al[mi][0] = p0.y;
                ah[mi][1] = p1.x; al[mi][1] = p1.y;
                ah[mi][2] = p2.x; al[mi][2] = p2.y;
                ah[mi][3] = p3.x; al[mi][3] = p3.y;
            }
            #pragma unroll
            for (int j = 0; j < NJ; j++) {
                uint4 b = ((uint4*)Wf)[(ksg * (FOUT / 8) + wx * 8 + j) * 32 + lane];
                #pragma unroll
                for (int mi = 0; mi < 2; mi++) {
                    mma8(acc[mi][j], al[mi], b.x, b.y);   // al*bh
                    mma8(acc[mi][j], ah[mi], b.z, b.w);   // ah*bl
                    mma8(acc[mi][j], ah[mi], b.x, b.y);   // ah*bh
                }
            }
        }
    }

    // epilogue: scale by dinv, optional accumulate
    int cb = wx * 64 + 2 * (lane & 3);
    #pragma unroll
    for (int mi = 0; mi < 2; mi++) {
        int r0 = base + wy * 32 + mi * 16 + (lane >> 2);
        int r1 = r0 + 8;
        float s0 = (r0 < NN) ? dinv[r0] : 0.f;
        float s1 = (r1 < NN) ? dinv[r1] : 0.f;
        #pragma unroll
        for (int j = 0; j < NJ; j++) {
            int c = cb + j * 8;
            if (r0 < NN) {
                float2* yp = (float2*)&Y[(size_t)r0 * FOUT + c];
                float2 o = make_float2(acc[mi][j][0] * s0, acc[mi][j][1] * s0);
                if (ACC) { float2 t = *yp; o.x += t.x; o.y += t.y; }
                *yp = o;
            }
            if (r1 < NN) {
                float2* yp = (float2*)&Y[(size_t)r1 * FOUT + c];
                float2 o = make_float2(acc[mi][j][2] * s1, acc[mi][j][3] * s1);
                if (ACC) { float2 t = *yp; o.x += t.x; o.y += t.y; }
                *yp = o;
            }
        }
    }
}

// ---------------- gather: out = silu(dinv*(sum_in y[src] + y[i]) + b) --------
template <int F>
__global__ void __launch_bounds__(256) k_gather(const float* __restrict__ y,
                                                const int* __restrict__ off,
                                                const int* __restrict__ csr,
                                                const float* __restrict__ dinv,
                                                const float* __restrict__ b,
                                                float* __restrict__ out) {
    int warp = (blockIdx.x * 256 + threadIdx.x) >> 5;
    int lane = threadIdx.x & 31;
    if (warp >= NN) return;
    int beg = off[warp], end = off[warp + 1];
    constexpr int V = F / 32;
    float acc[V];
    {
        const float* yr = y + (size_t)warp * F + lane * V;
        if constexpr (V == 4) {
            float4 t = *(const float4*)yr;
            acc[0] = t.x; acc[1] = t.y; acc[2] = t.z; acc[3] = t.w;
        } else {
            float2 t = *(const float2*)yr;
            acc[0] = t.x; acc[1] = t.y;
        }
    }
    for (int eb = beg; eb < end; eb += 32) {
        int n = end - eb; if (n > 32) n = 32;
        int s = (lane < n) ? __ldg(&csr[eb + lane]) : 0;
        for (int j = 0; j < n; j++) {
            int sj = __shfl_sync(0xffffffffu, s, j);
            const float* yr = y + (size_t)sj * F + lane * V;
            if constexpr (V == 4) {
                float4 t = *(const float4*)yr;
                acc[0] += t.x; acc[1] += t.y; acc[2] += t.z; acc[3] += t.w;
            } else {
                float2 t = *(const float2*)yr;
                acc[0] += t.x; acc[1] += t.y;
            }
        }
    }
    float di = dinv[warp];
    float ov[V];
    #pragma unroll
    for (int v = 0; v < V; v++) {
        float val = di * acc[v] + b[lane * V + v];
        ov[v] = val / (1.0f + expf(-val));
    }
    float* op = out + (size_t)warp * F + lane * V;
    if constexpr (V == 4) *(float4*)op = make_float4(ov[0], ov[1], ov[2], ov[3]);
    else *(float2*)op = make_float2(ov[0], ov[1]);
}

// ---------------- launch ----------------------------------------------------
extern "C" void kernel_launch(void* const* d_in, const int* in_sizes, int n_in,
                              void* d_out, int out_size) {
    const float* noise_x   = (const float*)d_in[0];
    const int*   edge      = (const int*)d_in[1];
    const int*   t_in      = (const int*)d_in[2];
    const int*   train_anm = (const int*)d_in[3];
    const int*   train_nrm = (const int*)d_in[4];
    const float* time_w1   = (const float*)d_in[5];
    const float* time_b1   = (const float*)d_in[6];
    const float* time_w2   = (const float*)d_in[7];
    const float* time_b2   = (const float*)d_in[8];
    const float* label_emb = (const float*)d_in[9];
    const float* w0 = (const float*)d_in[10];
    const float* b0 = (const float*)d_in[11];
    const float* w1 = (const float*)d_in[12];
    const float* b1 = (const float*)d_in[13];
    const float* w2 = (const float*)d_in[14];
    const float* b2 = (const float*)d_in[15];
    const float* w3 = (const float*)d_in[16];
    const float* b3 = (const float*)d_in[17];
    float* out = (float*)d_out;

    const int* src = edge;
    const int* dst = edge + EE;
    int n_anm = in_sizes[3];
    int n_nrm = in_sizes[4];
    int n_fl = (n_anm > n_nrm) ? n_anm : n_nrm;

    float *p_dinv, *p_temb, *p_y, *p_h0, *p_h1, *p_h2;
    int *p_deg, *p_flag, *p_off, *p_bsum, *p_cur, *p_csr;
    cudaGetSymbolAddress((void**)&p_dinv, g_dinv);
    cudaGetSymbolAddress((void**)&p_temb, g_temb);
    cudaGetSymbolAddress((void**)&p_y,    g_y);
    cudaGetSymbolAddress((void**)&p_h0,   g_h0);
    cudaGetSymbolAddress((void**)&p_h1,   g_h1);
    cudaGetSymbolAddress((void**)&p_h2,   g_h2);
    cudaGetSymbolAddress((void**)&p_deg,  g_deg);
    cudaGetSymbolAddress((void**)&p_flag, g_flag);
    cudaGetSymbolAddress((void**)&p_off,  g_off);
    cudaGetSymbolAddress((void**)&p_bsum, g_bsum);
    cudaGetSymbolAddress((void**)&p_cur,  g_cur);
    cudaGetSymbolAddress((void**)&p_csr,  g_csr);

    // dynamic smem sizes (words*4): Wfrag FIN*FOUT*2 + Xs BM*34
    const int SM_64_128  = (64 * 128 * 2 + 64 * 34) * 4;    // 74240 B
    const int SM_128_64  = (128 * 64 * 2 + 128 * 34) * 4;   // 82944 B
    cudaFuncSetAttribute(k_mma<64, 128, false, true>,  cudaFuncAttributeMaxDynamicSharedMemorySize, SM_64_128);
    cudaFuncSetAttribute(k_mma<64, 128, false, false>, cudaFuncAttributeMaxDynamicSharedMemorySize, SM_64_128);
    cudaFuncSetAttribute(k_mma<128, 64, false, false>, cudaFuncAttributeMaxDynamicSharedMemorySize, SM_128_64);
    cudaFuncSetAttribute(k_mma<128, 64, true,  false>, cudaFuncAttributeMaxDynamicSharedMemorySize, SM_128_64);

    const int TB = 256;
    const int GB64  = (NN + 63) / 64;      // FOUT=128 tiles
    const int GB128 = (NN + 127) / 128;    // FOUT=64 tiles
    const int GGATH = (NN * 32 + TB - 1) / TB;

    // launches 0-4 setup; launch 5 = layer-0 MMA (ncu -s 5 -c 1 target)
    k_init<<<(NN + TB - 1) / TB, TB>>>(p_deg, p_flag);
    k_deg<<<(EE + TB - 1) / TB, TB>>>(dst, p_deg);
    k_flags<<<(n_fl + TB - 1) / TB, TB>>>(train_anm, n_anm, train_nrm, n_nrm, p_flag);
    k_temb<<<1, DD>>>(t_in, time_w1, time_b1, time_w2, time_b2, p_temb);
    k_dinv<<<(NN + TB - 1) / TB, TB>>>(p_deg, p_dinv);

    // ---- layer 0 GEMM (fused x_t) ----
    k_mma<64, 128, false, true><<<GB64, 128, SM_64_128>>>(noise_x, w0, p_y, p_dinv,
                                                          label_emb, p_temb, p_flag);
    // ---- CSR build (overlaps conceptually; separate launches) ----
    k_scan1<<<NB, SB>>>(p_deg, p_off, p_bsum);
    k_scan2<<<1, 32>>>(p_bsum);
    k_scan3<<<(NN + TB - 1) / TB, TB>>>(p_off, p_bsum, p_cur);
    k_fill<<<(EE + TB - 1) / TB, TB>>>(src, dst, p_off, p_cur, p_csr);

    // ---- layer 0 gather -> h0 ----
    k_gather<128><<<GGATH, TB>>>(p_y, p_off, p_csr, p_dinv, b0, p_h0);

    // ---- layer 1 ----
    k_mma<128, 64, false, false><<<GB128, 128, SM_128_64>>>(p_h0, w1, p_y, p_dinv, 0, 0, 0);
    k_gather<64><<<GGATH, TB>>>(p_y, p_off, p_csr, p_dinv, b1, p_h1);

    // ---- layer 2 ----
    k_mma<64, 128, false, false><<<GB64, 128, SM_64_128>>>(p_h1, w2, p_y, p_dinv, 0, 0, 0);
    k_gather<128><<<GGATH, TB>>>(p_y, p_off, p_csr, p_dinv, b2, p_h2);

    // ---- layer 3: concat(h2,h0) @ w3 ----
    k_mma<128, 64, false, false><<<GB128, 128, SM_128_64>>>(p_h2, w3, p_y, p_dinv, 0, 0, 0);
    k_mma<128, 64, true,  false><<<GB128, 128, SM_128_64>>>(p_h0, w3 + 128 * 64, p_y, p_dinv, 0, 0, 0);
    k_gather<64><<<GGATH, TB>>>(p_y, p_off, p_csr, p_dinv, b3, out);
}

// round 5
// speedup vs baseline: 1.2405x; 1.2405x over previous
#include <cuda_runtime.h>
#include <math.h>

#define NN 100000
#define EE 1000000
#define DD 64
#define GG 128
#define SB 512
#define NB ((NN + SB - 1) / SB)
#define WFW 16384   // words per weight-fragment matrix (FIN*FOUT*2 = 8192*2)

// ---------------- scratch (device globals) -----------------------------------
__device__ float g_dinv[NN];
__device__ int   g_deg[NN];
__device__ int   g_flag[NN];
__device__ float g_temb[DD];
__device__ float g_y[NN * GG];
__device__ float g_h0[NN * GG];
__device__ float g_h1[NN * (GG / 2)];
__device__ float g_h2[NN * GG];
__device__ int   g_off[NN + 1];
__device__ int   g_bsum[NB + 1];
__device__ int   g_cur[NN];
__device__ int   g_csr[EE];
__device__ unsigned g_wf[5 * WFW];

// ---------------- small kernels ---------------------------------------------
__global__ void k_init(int* deg, int* flag) {
    int i = blockIdx.x * blockDim.x + threadIdx.x;
    if (i < NN) { deg[i] = 0; flag[i] = 0; }
}

__global__ void k_deg(const int* __restrict__ dst, int* deg) {
    int e = blockIdx.x * blockDim.x + threadIdx.x;
    if (e < EE) atomicAdd(&deg[dst[e]], 1);
}

__global__ void k_flags(const int* __restrict__ anm, int n_anm,
                        const int* __restrict__ nrm, int n_nrm, int* flag) {
    int i = blockIdx.x * blockDim.x + threadIdx.x;
    if (i < n_anm) atomicMax(&flag[anm[i]], 1);
    if (i < n_nrm) atomicMax(&flag[nrm[i]], 2);
}

__global__ void k_dinv(const int* __restrict__ deg, float* dinv) {
    int i = blockIdx.x * blockDim.x + threadIdx.x;
    if (i < NN) dinv[i] = rsqrtf((float)deg[i] + 1.0f);
}

// ---------------- tensor-core helpers ---------------------------------------
__device__ __forceinline__ unsigned f2tf(float f) {
    unsigned r; asm("cvt.rna.tf32.f32 %0, %1;" : "=r"(r) : "f"(f)); return r;
}
__device__ __forceinline__ void mma8(float* d, const unsigned* a, unsigned b0, unsigned b1) {
    asm volatile("mma.sync.aligned.m16n8k8.row.col.f32.tf32.tf32.f32 "
        "{%0,%1,%2,%3}, {%4,%5,%6,%7}, {%8,%9}, {%0,%1,%2,%3};"
        : "+f"(d[0]), "+f"(d[1]), "+f"(d[2]), "+f"(d[3])
        : "r"(a[0]), "r"(a[1]), "r"(a[2]), "r"(a[3]), "r"(b0), "r"(b1));
}

// ---------------- weight prep (once) + temb fused ----------------------------
// blocks 0-4: convert weight matrix to MMA B-fragment layout (hi/lo tf32).
// block 5: compute time-embedding MLP.
__global__ void k_wprep(const float* __restrict__ w0, const float* __restrict__ w1,
                        const float* __restrict__ w2, const float* __restrict__ w3,
                        unsigned* __restrict__ wf,
                        const int* __restrict__ t,
                        const float* __restrict__ tw1, const float* __restrict__ tb1,
                        const float* __restrict__ tw2, const float* __restrict__ tb2,
                        float* __restrict__ temb) {
    __shared__ float emb[DD];
    __shared__ float h[DD];
    int b = blockIdx.x;
    int tid = threadIdx.x;
    if (b == 5) {
        float tv;
        if (tid == 0) tv = (float)t[0];
        if (tid < 32) {
            tv = (float)t[0];
            float freq = expf((float)tid * (-logf(10000.0f) / 31.0f));
            float arg = tv * freq;
            emb[tid] = sinf(arg);
            emb[tid + 32] = cosf(arg);
        }
        __syncthreads();
        if (tid < DD) {
            float acc = tb1[tid];
            #pragma unroll
            for (int k = 0; k < DD; k++) acc += emb[k] * tw1[k * DD + tid];
            acc = acc / (1.0f + expf(-acc));
            h[tid] = acc;
        }
        __syncthreads();
        if (tid < DD) {
            float acc2 = tb2[tid];
            #pragma unroll
            for (int k = 0; k < DD; k++) acc2 += h[k] * tw2[k * DD + tid];
            temb[tid] = acc2;
        }
        return;
    }
    const float* Wg;
    int fout;
    switch (b) {
        case 0: Wg = w0; fout = 128; break;
        case 1: Wg = w1; fout = 64;  break;
        case 2: Wg = w2; fout = 128; break;
        case 3: Wg = w3; fout = 64;  break;
        default: Wg = w3 + 128 * 64; fout = 64; break;
    }
    uint4* out = (uint4*)(wf + b * WFW);
    const int total = WFW / 4;                 // 4096 uint4 per matrix
    int jt = fout / 8;
    for (int p = tid; p < total; p += blockDim.x) {
        int ks = p / (jt * 32);
        int rem = p % (jt * 32);
        int j = rem / 32;
        int ln = rem % 32;
        int col = j * 8 + (ln >> 2);
        int kr = ks * 8 + (ln & 3);
        float v0 = __ldg(&Wg[kr * fout + col]);
        float v1 = __ldg(&Wg[(kr + 4) * fout + col]);
        unsigned h0 = f2tf(v0), h1 = f2tf(v1);
        unsigned l0 = f2tf(v0 - __uint_as_float(h0));
        unsigned l1 = f2tf(v1 - __uint_as_float(h1));
        out[p] = make_uint4(h0, h1, l0, l1);
    }
}

// ---------------- CSR build --------------------------------------------------
__global__ void k_scan1(const int* __restrict__ deg, int* off, int* bsum) {
    __shared__ int sh[SB];
    int i = blockIdx.x * SB + threadIdx.x;
    int v = (i < NN) ? deg[i] : 0;
    sh[threadIdx.x] = v;
    __syncthreads();
    for (int s = 1; s < SB; s <<= 1) {
        int t = (threadIdx.x >= s) ? sh[threadIdx.x - s] : 0;
        __syncthreads();
        sh[threadIdx.x] += t;
        __syncthreads();
    }
    if (i < NN) off[i] = sh[threadIdx.x] - v;
    if (threadIdx.x == SB - 1) bsum[blockIdx.x] = sh[SB - 1];
}

__global__ void k_scan2(int* bsum) {
    if (threadIdx.x == 0) {
        int acc = 0;
        for (int b = 0; b < NB; b++) { int t = bsum[b]; bsum[b] = acc; acc += t; }
    }
}

__global__ void k_scan3(int* off, const int* __restrict__ bsum, int* cur) {
    int i = blockIdx.x * blockDim.x + threadIdx.x;
    if (i < NN) { off[i] += bsum[i / SB]; cur[i] = 0; }
    if (i == 0) off[NN] = EE;
}

__global__ void k_fill(const int* __restrict__ src, const int* __restrict__ dst,
                       const int* __restrict__ off, int* cur, int* csr) {
    int e = blockIdx.x * blockDim.x + threadIdx.x;
    if (e < EE) {
        int d = dst[e];
        int p = off[d] + atomicAdd(&cur[d], 1);
        csr[p] = src[e];
    }
}

// ---------------- 3xTF32 MMA GEMM (W-fragments from global) ------------------
// Y[r,c] (+)= (sum_k X[r,k]*W[k,c]) * dinv[r]
template <int FIN, int FOUT, bool ACC, bool FUSE0>
__global__ void __launch_bounds__(128) k_mma(const float* __restrict__ X,
                                             const unsigned* __restrict__ WfG,
                                             float* __restrict__ Y,
                                             const float* __restrict__ dinv,
                                             const float* __restrict__ lemb,
                                             const float* __restrict__ temb,
                                             const int* __restrict__ flag) {
    constexpr int BM = (FOUT == 128) ? 64 : 128;
    constexpr int BK = 16;
    constexpr int NJ = 8;
    constexpr int XROW = BK * 2 + 2;   // hi/lo interleaved + pad
    __shared__ unsigned Xs[BM * XROW];
    __shared__ float temb_s[DD], l0_s[DD], l1_s[DD];

    int tid = threadIdx.x;
    int lane = tid & 31, wid = tid >> 5;
    int wx = (FOUT == 128) ? (wid & 1) : 0;
    int wy = (FOUT == 128) ? (wid >> 1) : wid;

    if (FUSE0 && tid < DD) {
        temb_s[tid] = temb[tid];
        l0_s[tid] = lemb[tid];
        l1_s[tid] = lemb[DD + tid];
    }

    int base = blockIdx.x * BM;
    float acc[2][NJ][4];
    #pragma unroll
    for (int mi = 0; mi < 2; mi++)
        #pragma unroll
        for (int j = 0; j < NJ; j++)
            #pragma unroll
            for (int q = 0; q < 4; q++) acc[mi][j][q] = 0.f;

    const uint4* Wf4 = (const uint4*)WfG;

    for (int kc = 0; kc < FIN; kc += BK) {
        __syncthreads();
        for (int q = tid; q < BM * (BK / 4); q += 128) {
            int r = q / (BK / 4), kq = q % (BK / 4);
            int gr = base + r; if (gr >= NN) gr = NN - 1;
            float4 v = *(const float4*)&X[(size_t)gr * FIN + kc + kq * 4];
            float vv[4] = {v.x, v.y, v.z, v.w};
            if (FUSE0) {
                int fl = flag[gr];
                #pragma unroll
                for (int i = 0; i < 4; i++) {
                    int kk = kc + kq * 4 + i;
                    vv[i] += temb_s[kk];
                    if (fl == 1) vv[i] += l1_s[kk];
                    else if (fl == 2) vv[i] += l0_s[kk];
                }
            }
            #pragma unroll
            for (int i = 0; i < 4; i++) {
                unsigned h = f2tf(vv[i]);
                unsigned l = f2tf(vv[i] - __uint_as_float(h));
                Xs[r * XROW + (kq * 4 + i) * 2] = h;
                Xs[r * XROW + (kq * 4 + i) * 2 + 1] = l;
            }
        }
        __syncthreads();
        #pragma unroll
        for (int kl = 0; kl < BK; kl += 8) {
            int ksg = (kc + kl) >> 3;
            unsigned ah[2][4], al[2][4];
            #pragma unroll
            for (int mi = 0; mi < 2; mi++) {
                int r = wy * 32 + mi * 16 + (lane >> 2);
                int k0 = kl + (lane & 3);
                uint2 p0 = *(uint2*)&Xs[r * XROW + k0 * 2];
                uint2 p1 = *(uint2*)&Xs[(r + 8) * XROW + k0 * 2];
                uint2 p2 = *(uint2*)&Xs[r * XROW + (k0 + 4) * 2];
                uint2 p3 = *(uint2*)&Xs[(r + 8) * XROW + (k0 + 4) * 2];
                ah[mi][0] = p0.x; al[mi][0] = p0.y;
                ah[mi][1] = p1.x; al[mi][1] = p1.y;
                ah[mi][2] = p2.x; al[mi][2] = p2.y;
                ah[mi][3] = p3.x; al[mi][3] = p3.y;
            }
            #pragma unroll
            for (int j = 0; j < NJ; j++) {
                uint4 b = __ldg(&Wf4[(ksg * (FOUT / 8) + wx * 8 + j) * 32 + lane]);
                #pragma unroll
                for (int mi = 0; mi < 2; mi++) {
                    mma8(acc[mi][j], al[mi], b.x, b.y);   // al*bh
                    mma8(acc[mi][j], ah[mi], b.z, b.w);   // ah*bl
                    mma8(acc[mi][j], ah[mi], b.x, b.y);   // ah*bh
                }
            }
        }
    }

    int cb = wx * 64 + 2 * (lane & 3);
    #pragma unroll
    for (int mi = 0; mi < 2; mi++) {
        int r0 = base + wy * 32 + mi * 16 + (lane >> 2);
        int r1 = r0 + 8;
        float s0 = (r0 < NN) ? dinv[r0] : 0.f;
        float s1 = (r1 < NN) ? dinv[r1] : 0.f;
        #pragma unroll
        for (int j = 0; j < NJ; j++) {
            int c = cb + j * 8;
            if (r0 < NN) {
                float2* yp = (float2*)&Y[(size_t)r0 * FOUT + c];
                float2 o = make_float2(acc[mi][j][0] * s0, acc[mi][j][1] * s0);
                if (ACC) { float2 t = *yp; o.x += t.x; o.y += t.y; }
                *yp = o;
            }
            if (r1 < NN) {
                float2* yp = (float2*)&Y[(size_t)r1 * FOUT + c];
                float2 o = make_float2(acc[mi][j][2] * s1, acc[mi][j][3] * s1);
                if (ACC) { float2 t = *yp; o.x += t.x; o.y += t.y; }
                *yp = o;
            }
        }
    }
}

// ---------------- gather: out = silu(dinv*(sum_in y[src] + y[i]) + b) --------
template <int F>
__global__ void __launch_bounds__(256) k_gather(const float* __restrict__ y,
                                                const int* __restrict__ off,
                                                const int* __restrict__ csr,
                                                const float* __restrict__ dinv,
                                                const float* __restrict__ b,
                                                float* __restrict__ out) {
    int warp = (blockIdx.x * 256 + threadIdx.x) >> 5;
    int lane = threadIdx.x & 31;
    if (warp >= NN) return;
    int beg = off[warp], end = off[warp + 1];
    constexpr int V = F / 32;
    float acc[V];
    {
        const float* yr = y + (size_t)warp * F + lane * V;
        if constexpr (V == 4) {
            float4 t = *(const float4*)yr;
            acc[0] = t.x; acc[1] = t.y; acc[2] = t.z; acc[3] = t.w;
        } else {
            float2 t = *(const float2*)yr;
            acc[0] = t.x; acc[1] = t.y;
        }
    }
    for (int eb = beg; eb < end; eb += 32) {
        int n = end - eb; if (n > 32) n = 32;
        int s = (lane < n) ? __ldg(&csr[eb + lane]) : 0;
        for (int j = 0; j < n; j++) {
            int sj = __shfl_sync(0xffffffffu, s, j);
            const float* yr = y + (size_t)sj * F + lane * V;
            if constexpr (V == 4) {
                float4 t = *(const float4*)yr;
                acc[0] += t.x; acc[1] += t.y; acc[2] += t.z; acc[3] += t.w;
            } else {
                float2 t = *(const float2*)yr;
                acc[0] += t.x; acc[1] += t.y;
            }
        }
    }
    float di = dinv[warp];
    float ov[V];
    #pragma unroll
    for (int v = 0; v < V; v++) {
        float val = di * acc[v] + b[lane * V + v];
        ov[v] = val / (1.0f + expf(-val));
    }
    float* op = out + (size_t)warp * F + lane * V;
    if constexpr (V == 4) *(float4*)op = make_float4(ov[0], ov[1], ov[2], ov[3]);
    else *(float2*)op = make_float2(ov[0], ov[1]);
}

// ---------------- launch ----------------------------------------------------
extern "C" void kernel_launch(void* const* d_in, const int* in_sizes, int n_in,
                              void* d_out, int out_size) {
    const float* noise_x   = (const float*)d_in[0];
    const int*   edge      = (const int*)d_in[1];
    const int*   t_in      = (const int*)d_in[2];
    const int*   train_anm = (const int*)d_in[3];
    const int*   train_nrm = (const int*)d_in[4];
    const float* time_w1   = (const float*)d_in[5];
    const float* time_b1   = (const float*)d_in[6];
    const float* time_w2   = (const float*)d_in[7];
    const float* time_b2   = (const float*)d_in[8];
    const float* label_emb = (const float*)d_in[9];
    const float* w0 = (const float*)d_in[10];
    const float* b0 = (const float*)d_in[11];
    const float* w1 = (const float*)d_in[12];
    const float* b1 = (const float*)d_in[13];
    const float* w2 = (const float*)d_in[14];
    const float* b2 = (const float*)d_in[15];
    const float* w3 = (const float*)d_in[16];
    const float* b3 = (const float*)d_in[17];
    float* out = (float*)d_out;

    const int* src = edge;
    const int* dst = edge + EE;
    int n_anm = in_sizes[3];
    int n_nrm = in_sizes[4];
    int n_fl = (n_anm > n_nrm) ? n_anm : n_nrm;

    float *p_dinv, *p_temb, *p_y, *p_h0, *p_h1, *p_h2;
    int *p_deg, *p_flag, *p_off, *p_bsum, *p_cur, *p_csr;
    unsigned *p_wf;
    cudaGetSymbolAddress((void**)&p_dinv, g_dinv);
    cudaGetSymbolAddress((void**)&p_temb, g_temb);
    cudaGetSymbolAddress((void**)&p_y,    g_y);
    cudaGetSymbolAddress((void**)&p_h0,   g_h0);
    cudaGetSymbolAddress((void**)&p_h1,   g_h1);
    cudaGetSymbolAddress((void**)&p_h2,   g_h2);
    cudaGetSymbolAddress((void**)&p_deg,  g_deg);
    cudaGetSymbolAddress((void**)&p_flag, g_flag);
    cudaGetSymbolAddress((void**)&p_off,  g_off);
    cudaGetSymbolAddress((void**)&p_bsum, g_bsum);
    cudaGetSymbolAddress((void**)&p_cur,  g_cur);
    cudaGetSymbolAddress((void**)&p_csr,  g_csr);
    cudaGetSymbolAddress((void**)&p_wf,   g_wf);

    const int TB = 256;
    const int GB64  = (NN + 63) / 64;      // FOUT=128 tiles (BM=64)
    const int GB128 = (NN + 127) / 128;    // FOUT=64 tiles (BM=128)
    const int GGATH = (NN * 32 + TB - 1) / TB;

    // launches: 0 init, 1 deg, 2 wprep(+temb), 3 dinv, 4 flags, 5 gemm0 (ncu target)
    k_init<<<(NN + TB - 1) / TB, TB>>>(p_deg, p_flag);
    k_deg<<<(EE + TB - 1) / TB, TB>>>(dst, p_deg);
    k_wprep<<<6, 256>>>(w0, w1, w2, w3, p_wf,
                        t_in, time_w1, time_b1, time_w2, time_b2, p_temb);
    k_dinv<<<(NN + TB - 1) / TB, TB>>>(p_deg, p_dinv);
    k_flags<<<(n_fl + TB - 1) / TB, TB>>>(train_anm, n_anm, train_nrm, n_nrm, p_flag);

    // ---- layer 0 GEMM (fused x_t) ----
    k_mma<64, 128, false, true><<<GB64, 128>>>(noise_x, p_wf + 0 * WFW, p_y, p_dinv,
                                               label_emb, p_temb, p_flag);
    // ---- CSR build ----
    k_scan1<<<NB, SB>>>(p_deg, p_off, p_bsum);
    k_scan2<<<1, 32>>>(p_bsum);
    k_scan3<<<(NN + TB - 1) / TB, TB>>>(p_off, p_bsum, p_cur);
    k_fill<<<(EE + TB - 1) / TB, TB>>>(src, dst, p_off, p_cur, p_csr);

    // ---- layer 0 gather -> h0 ----
    k_gather<128><<<GGATH, TB>>>(p_y, p_off, p_csr, p_dinv, b0, p_h0);

    // ---- layer 1 ----
    k_mma<128, 64, false, false><<<GB128, 128>>>(p_h0, p_wf + 1 * WFW, p_y, p_dinv, 0, 0, 0);
    k_gather<64><<<GGATH, TB>>>(p_y, p_off, p_csr, p_dinv, b1, p_h1);

    // ---- layer 2 ----
    k_mma<64, 128, false, false><<<GB64, 128>>>(p_h1, p_wf + 2 * WFW, p_y, p_dinv, 0, 0, 0);
    k_gather<128><<<GGATH, TB>>>(p_y, p_off, p_csr, p_dinv, b2, p_h2);

    // ---- layer 3: concat(h2,h0) @ w3 ----
    k_mma<128, 64, false, false><<<GB128, 128>>>(p_h2, p_wf + 3 * WFW, p_y, p_dinv, 0, 0, 0);
    k_mma<128, 64, true,  false><<<GB128, 128>>>(p_h0, p_wf + 4 * WFW, p_y, p_dinv, 0, 0, 0);
    k_gather<64><<<GGATH, TB>>>(p_y, p_off, p_csr, p_dinv, b3, out);
}

// round 6
// speedup vs baseline: 1.2957x; 1.0445x over previous
#include <cuda_runtime.h>
#include <math.h>

#define NN 100000
#define EE 1000000
#define DD 64
#define GG 128
#define SB 512
#define NB ((NN + SB - 1) / SB)
#define WFW 16384   // words per weight-fragment matrix

// ---------------- scratch (device globals) -----------------------------------
__device__ int   g_deg[NN];
__device__ int   g_flag[NN];
__device__ float g_temb[DD];
__device__ float g_y[NN * GG];
__device__ float g_h0[NN * GG];
__device__ float g_h1[NN * (GG / 2)];
__device__ float g_h2[NN * GG];
__device__ int   g_off[NN + 1];
__device__ int   g_bsum[NB + 1];
__device__ int   g_cur[NN];
__device__ int   g_csr[EE];
__device__ unsigned g_wf[5 * WFW];

// ---------------- small kernels ---------------------------------------------
__global__ void k_init(int* deg, int* flag, int* cur) {
    int i = blockIdx.x * blockDim.x + threadIdx.x;
    if (i < NN) { deg[i] = 0; flag[i] = 0; cur[i] = 0; }
}

__global__ void k_deg(const int* __restrict__ dst, int* deg) {
    int e = blockIdx.x * blockDim.x + threadIdx.x;
    if (e < EE) atomicAdd(&deg[dst[e]], 1);
}

// ---------------- tensor-core helpers ---------------------------------------
__device__ __forceinline__ unsigned f2tf(float f) {
    unsigned r; asm("cvt.rna.tf32.f32 %0, %1;" : "=r"(r) : "f"(f)); return r;
}
__device__ __forceinline__ void mma8(float* d, const unsigned* a, unsigned b0, unsigned b1) {
    asm volatile("mma.sync.aligned.m16n8k8.row.col.f32.tf32.tf32.f32 "
        "{%0,%1,%2,%3}, {%4,%5,%6,%7}, {%8,%9}, {%0,%1,%2,%3};"
        : "+f"(d[0]), "+f"(d[1]), "+f"(d[2]), "+f"(d[3])
        : "r"(a[0]), "r"(a[1]), "r"(a[2]), "r"(a[3]), "r"(b0), "r"(b1));
}

// ---------------- weight prep + temb + flag scatter (one kernel) -------------
// blocks 0-4: weight->fragment conversion; block 5: temb MLP; blocks >=6: flags
__global__ void k_wprep(const float* __restrict__ w0, const float* __restrict__ w1,
                        const float* __restrict__ w2, const float* __restrict__ w3,
                        unsigned* __restrict__ wf,
                        const int* __restrict__ t,
                        const float* __restrict__ tw1, const float* __restrict__ tb1,
                        const float* __restrict__ tw2, const float* __restrict__ tb2,
                        float* __restrict__ temb,
                        const int* __restrict__ anm, int n_anm,
                        const int* __restrict__ nrm, int n_nrm, int* flag) {
    __shared__ float emb[DD];
    __shared__ float h[DD];
    int b = blockIdx.x;
    int tid = threadIdx.x;
    if (b >= 6) {
        int i = (b - 6) * 256 + tid;
        if (i < n_anm) atomicMax(&flag[anm[i]], 1);
        if (i < n_nrm) atomicMax(&flag[nrm[i]], 2);
        return;
    }
    if (b == 5) {
        if (tid < 32) {
            float tv = (float)t[0];
            float freq = expf((float)tid * (-logf(10000.0f) / 31.0f));
            float arg = tv * freq;
            emb[tid] = sinf(arg);
            emb[tid + 32] = cosf(arg);
        }
        __syncthreads();
        if (tid < DD) {
            float acc = tb1[tid];
            #pragma unroll
            for (int k = 0; k < DD; k++) acc += emb[k] * tw1[k * DD + tid];
            acc = acc / (1.0f + expf(-acc));
            h[tid] = acc;
        }
        __syncthreads();
        if (tid < DD) {
            float acc2 = tb2[tid];
            #pragma unroll
            for (int k = 0; k < DD; k++) acc2 += h[k] * tw2[k * DD + tid];
            temb[tid] = acc2;
        }
        return;
    }
    const float* Wg;
    int fout;
    switch (b) {
        case 0: Wg = w0; fout = 128; break;
        case 1: Wg = w1; fout = 64;  break;
        case 2: Wg = w2; fout = 128; break;
        case 3: Wg = w3; fout = 64;  break;
        default: Wg = w3 + 128 * 64; fout = 64; break;
    }
    uint4* out = (uint4*)(wf + b * WFW);
    const int total = WFW / 4;
    int jt = fout / 8;
    for (int p = tid; p < total; p += blockDim.x) {
        int ks = p / (jt * 32);
        int rem = p % (jt * 32);
        int j = rem / 32;
        int ln = rem % 32;
        int col = j * 8 + (ln >> 2);
        int kr = ks * 8 + (ln & 3);
        float v0 = __ldg(&Wg[kr * fout + col]);
        float v1 = __ldg(&Wg[(kr + 4) * fout + col]);
        unsigned h0 = f2tf(v0), h1 = f2tf(v1);
        unsigned l0 = f2tf(v0 - __uint_as_float(h0));
        unsigned l1 = f2tf(v1 - __uint_as_float(h1));
        out[p] = make_uint4(h0, h1, l0, l1);
    }
}

// ---------------- CSR build --------------------------------------------------
__global__ void k_scan1(const int* __restrict__ deg, int* off, int* bsum) {
    __shared__ int sh[SB];
    int i = blockIdx.x * SB + threadIdx.x;
    int v = (i < NN) ? deg[i] : 0;
    sh[threadIdx.x] = v;
    __syncthreads();
    for (int s = 1; s < SB; s <<= 1) {
        int t = (threadIdx.x >= s) ? sh[threadIdx.x - s] : 0;
        __syncthreads();
        sh[threadIdx.x] += t;
        __syncthreads();
    }
    if (i < NN) off[i] = sh[threadIdx.x] - v;
    if (threadIdx.x == SB - 1) bsum[blockIdx.x] = sh[SB - 1];
}

__global__ void k_scan2(int* bsum) {
    if (threadIdx.x == 0) {
        int acc = 0;
        for (int b = 0; b < NB; b++) { int t = bsum[b]; bsum[b] = acc; acc += t; }
    }
}

__global__ void k_scan3(int* off, const int* __restrict__ bsum) {
    int i = blockIdx.x * blockDim.x + threadIdx.x;
    if (i < NN) off[i] += bsum[i / SB];
    if (i == 0) off[NN] = EE;
}

__global__ void k_fill(const int* __restrict__ src, const int* __restrict__ dst,
                       const int* __restrict__ off, int* cur, int* csr) {
    int e = blockIdx.x * blockDim.x + threadIdx.x;
    if (e < EE) {
        int d = dst[e];
        int p = off[d] + atomicAdd(&cur[d], 1);
        csr[p] = src[e];
    }
}

// ---------------- 3xTF32 MMA GEMM (W-fragments from global) ------------------
// Y[r,c] (+)= (sum_k X[r,k]*W[k,c]) * rsqrt(deg[r]+1)
template <int FIN, int FOUT, bool ACC, bool FUSE0>
__global__ void __launch_bounds__(128) k_mma(const float* __restrict__ X,
                                             const unsigned* __restrict__ WfG,
                                             float* __restrict__ Y,
                                             const int* __restrict__ deg,
                                             const float* __restrict__ lemb,
                                             const float* __restrict__ temb,
                                             const int* __restrict__ flag) {
    constexpr int BM = (FOUT == 128) ? 64 : 128;
    constexpr int BK = 16;
    constexpr int NJ = 8;
    constexpr int XROW = BK * 2 + 2;
    __shared__ unsigned Xs[BM * XROW];
    __shared__ float temb_s[DD], l0_s[DD], l1_s[DD];

    int tid = threadIdx.x;
    int lane = tid & 31, wid = tid >> 5;
    int wx = (FOUT == 128) ? (wid & 1) : 0;
    int wy = (FOUT == 128) ? (wid >> 1) : wid;

    if (FUSE0 && tid < DD) {
        temb_s[tid] = temb[tid];
        l0_s[tid] = lemb[tid];
        l1_s[tid] = lemb[DD + tid];
    }

    int base = blockIdx.x * BM;
    float acc[2][NJ][4];
    #pragma unroll
    for (int mi = 0; mi < 2; mi++)
        #pragma unroll
        for (int j = 0; j < NJ; j++)
            #pragma unroll
            for (int q = 0; q < 4; q++) acc[mi][j][q] = 0.f;

    const uint4* Wf4 = (const uint4*)WfG;

    for (int kc = 0; kc < FIN; kc += BK) {
        __syncthreads();
        for (int q = tid; q < BM * (BK / 4); q += 128) {
            int r = q / (BK / 4), kq = q % (BK / 4);
            int gr = base + r; if (gr >= NN) gr = NN - 1;
            float4 v = *(const float4*)&X[(size_t)gr * FIN + kc + kq * 4];
            float vv[4] = {v.x, v.y, v.z, v.w};
            if (FUSE0) {
                int fl = flag[gr];
                #pragma unroll
                for (int i = 0; i < 4; i++) {
                    int kk = kc + kq * 4 + i;
                    vv[i] += temb_s[kk];
                    if (fl == 1) vv[i] += l1_s[kk];
                    else if (fl == 2) vv[i] += l0_s[kk];
                }
            }
            #pragma unroll
            for (int i = 0; i < 4; i++) {
                unsigned h = f2tf(vv[i]);
                unsigned l = f2tf(vv[i] - __uint_as_float(h));
                Xs[r * XROW + (kq * 4 + i) * 2] = h;
                Xs[r * XROW + (kq * 4 + i) * 2 + 1] = l;
            }
        }
        __syncthreads();
        #pragma unroll
        for (int kl = 0; kl < BK; kl += 8) {
            int ksg = (kc + kl) >> 3;
            unsigned ah[2][4], al[2][4];
            #pragma unroll
            for (int mi = 0; mi < 2; mi++) {
                int r = wy * 32 + mi * 16 + (lane >> 2);
                int k0 = kl + (lane & 3);
                uint2 p0 = *(uint2*)&Xs[r * XROW + k0 * 2];
                uint2 p1 = *(uint2*)&Xs[(r + 8) * XROW + k0 * 2];
                uint2 p2 = *(uint2*)&Xs[r * XROW + (k0 + 4) * 2];
                uint2 p3 = *(uint2*)&Xs[(r + 8) * XROW + (k0 + 4) * 2];
                ah[mi][0] = p0.x; al[mi][0] = p0.y;
                ah[mi][1] = p1.x; al[mi][1] = p1.y;
                ah[mi][2] = p2.x; al[mi][2] = p2.y;
                ah[mi][3] = p3.x; al[mi][3] = p3.y;
            }
            #pragma unroll
            for (int j = 0; j < NJ; j++) {
                uint4 b = __ldg(&Wf4[(ksg * (FOUT / 8) + wx * 8 + j) * 32 + lane]);
                #pragma unroll
                for (int mi = 0; mi < 2; mi++) {
                    mma8(acc[mi][j], al[mi], b.x, b.y);
                    mma8(acc[mi][j], ah[mi], b.z, b.w);
                    mma8(acc[mi][j], ah[mi], b.x, b.y);
                }
            }
        }
    }

    int cb = wx * 64 + 2 * (lane & 3);
    #pragma unroll
    for (int mi = 0; mi < 2; mi++) {
        int r0 = base + wy * 32 + mi * 16 + (lane >> 2);
        int r1 = r0 + 8;
        float s0 = (r0 < NN) ? rsqrtf((float)deg[r0] + 1.0f) : 0.f;
        float s1 = (r1 < NN) ? rsqrtf((float)deg[r1] + 1.0f) : 0.f;
        #pragma unroll
        for (int j = 0; j < NJ; j++) {
            int c = cb + j * 8;
            if (r0 < NN) {
                float2* yp = (float2*)&Y[(size_t)r0 * FOUT + c];
                float2 o = make_float2(acc[mi][j][0] * s0, acc[mi][j][1] * s0);
                if (ACC) { float2 t = *yp; o.x += t.x; o.y += t.y; }
                *yp = o;
            }
            if (r1 < NN) {
                float2* yp = (float2*)&Y[(size_t)r1 * FOUT + c];
                float2 o = make_float2(acc[mi][j][2] * s1, acc[mi][j][3] * s1);
                if (ACC) { float2 t = *yp; o.x += t.x; o.y += t.y; }
                *yp = o;
            }
        }
    }
}

// ---------------- gather: out = silu(dinv*(sum_in y[src] + y[i]) + b) --------
template <int F>
__global__ void __launch_bounds__(256) k_gather(const float* __restrict__ y,
                                                const int* __restrict__ off,
                                                const int* __restrict__ csr,
                                                const int* __restrict__ deg,
                                                const float* __restrict__ b,
                                                float* __restrict__ out) {
    int warp = (blockIdx.x * 256 + threadIdx.x) >> 5;
    int lane = threadIdx.x & 31;
    if (warp >= NN) return;
    int beg = off[warp], end = off[warp + 1];
    constexpr int V = F / 32;
    float acc[V];
    {
        const float* yr = y + (size_t)warp * F + lane * V;
        if constexpr (V == 4) {
            float4 t = *(const float4*)yr;
            acc[0] = t.x; acc[1] = t.y; acc[2] = t.z; acc[3] = t.w;
        } else {
            float2 t = *(const float2*)yr;
            acc[0] = t.x; acc[1] = t.y;
        }
    }
    for (int eb = beg; eb < end; eb += 32) {
        int n = end - eb; if (n > 32) n = 32;
        int s = (lane < n) ? __ldg(&csr[eb + lane]) : 0;
        int j = 0;
        // 4-wide unrolled: 4 independent row loads in flight
        for (; j + 4 <= n; j += 4) {
            int s0 = __shfl_sync(0xffffffffu, s, j);
            int s1 = __shfl_sync(0xffffffffu, s, j + 1);
            int s2 = __shfl_sync(0xffffffffu, s, j + 2);
            int s3 = __shfl_sync(0xffffffffu, s, j + 3);
            if constexpr (V == 4) {
                float4 t0 = *(const float4*)(y + (size_t)s0 * F + lane * 4);
                float4 t1 = *(const float4*)(y + (size_t)s1 * F + lane * 4);
                float4 t2 = *(const float4*)(y + (size_t)s2 * F + lane * 4);
                float4 t3 = *(const float4*)(y + (size_t)s3 * F + lane * 4);
                acc[0] += (t0.x + t1.x) + (t2.x + t3.x);
                acc[1] += (t0.y + t1.y) + (t2.y + t3.y);
                acc[2] += (t0.z + t1.z) + (t2.z + t3.z);
                acc[3] += (t0.w + t1.w) + (t2.w + t3.w);
            } else {
                float2 t0 = *(const float2*)(y + (size_t)s0 * F + lane * 2);
                float2 t1 = *(const float2*)(y + (size_t)s1 * F + lane * 2);
                float2 t2 = *(const float2*)(y + (size_t)s2 * F + lane * 2);
                float2 t3 = *(const float2*)(y + (size_t)s3 * F + lane * 2);
                acc[0] += (t0.x + t1.x) + (t2.x + t3.x);
                acc[1] += (t0.y + t1.y) + (t2.y + t3.y);
            }
        }
        for (; j < n; j++) {
            int sj = __shfl_sync(0xffffffffu, s, j);
            const float* yr = y + (size_t)sj * F + lane * V;
            if constexpr (V == 4) {
                float4 t = *(const float4*)yr;
                acc[0] += t.x; acc[1] += t.y; acc[2] += t.z; acc[3] += t.w;
            } else {
                float2 t = *(const float2*)yr;
                acc[0] += t.x; acc[1] += t.y;
            }
        }
    }
    float di = rsqrtf((float)deg[warp] + 1.0f);
    float ov[V];
    #pragma unroll
    for (int v = 0; v < V; v++) {
        float val = di * acc[v] + b[lane * V + v];
        ov[v] = val / (1.0f + expf(-val));
    }
    float* op = out + (size_t)warp * F + lane * V;
    if constexpr (V == 4) *(float4*)op = make_float4(ov[0], ov[1], ov[2], ov[3]);
    else *(float2*)op = make_float2(ov[0], ov[1]);
}

// ---------------- launch ----------------------------------------------------
extern "C" void kernel_launch(void* const* d_in, const int* in_sizes, int n_in,
                              void* d_out, int out_size) {
    const float* noise_x   = (const float*)d_in[0];
    const int*   edge      = (const int*)d_in[1];
    const int*   t_in      = (const int*)d_in[2];
    const int*   train_anm = (const int*)d_in[3];
    const int*   train_nrm = (const int*)d_in[4];
    const float* time_w1   = (const float*)d_in[5];
    const float* time_b1   = (const float*)d_in[6];
    const float* time_w2   = (const float*)d_in[7];
    const float* time_b2   = (const float*)d_in[8];
    const float* label_emb = (const float*)d_in[9];
    const float* w0 = (const float*)d_in[10];
    const float* b0 = (const float*)d_in[11];
    const float* w1 = (const float*)d_in[12];
    const float* b1 = (const float*)d_in[13];
    const float* w2 = (const float*)d_in[14];
    const float* b2 = (const float*)d_in[15];
    const float* w3 = (const float*)d_in[16];
    const float* b3 = (const float*)d_in[17];
    float* out = (float*)d_out;

    const int* src = edge;
    const int* dst = edge + EE;
    int n_anm = in_sizes[3];
    int n_nrm = in_sizes[4];
    int n_fl = (n_anm > n_nrm) ? n_anm : n_nrm;

    float *p_temb, *p_y, *p_h0, *p_h1, *p_h2;
    int *p_deg, *p_flag, *p_off, *p_bsum, *p_cur, *p_csr;
    unsigned *p_wf;
    cudaGetSymbolAddress((void**)&p_temb, g_temb);
    cudaGetSymbolAddress((void**)&p_y,    g_y);
    cudaGetSymbolAddress((void**)&p_h0,   g_h0);
    cudaGetSymbolAddress((void**)&p_h1,   g_h1);
    cudaGetSymbolAddress((void**)&p_h2,   g_h2);
    cudaGetSymbolAddress((void**)&p_deg,  g_deg);
    cudaGetSymbolAddress((void**)&p_flag, g_flag);
    cudaGetSymbolAddress((void**)&p_off,  g_off);
    cudaGetSymbolAddress((void**)&p_bsum, g_bsum);
    cudaGetSymbolAddress((void**)&p_cur,  g_cur);
    cudaGetSymbolAddress((void**)&p_csr,  g_csr);
    cudaGetSymbolAddress((void**)&p_wf,   g_wf);

    const int TB = 256;
    const int GB64  = (NN + 63) / 64;
    const int GB128 = (NN + 127) / 128;
    const int GGATH = (NN * 32 + TB - 1) / TB;

    // 0 init, 1 deg, 2 wprep(+temb+flags), 3 gemm0  <- profiler captures idx 3
    k_init<<<(NN + TB - 1) / TB, TB>>>(p_deg, p_flag, p_cur);
    k_deg<<<(EE + TB - 1) / TB, TB>>>(dst, p_deg);
    k_wprep<<<6 + (n_fl + 255) / 256, 256>>>(w0, w1, w2, w3, p_wf,
                        t_in, time_w1, time_b1, time_w2, time_b2, p_temb,
                        train_anm, n_anm, train_nrm, n_nrm, p_flag);
    k_mma<64, 128, false, true><<<GB64, 128>>>(noise_x, p_wf + 0 * WFW, p_y, p_deg,
                                               label_emb, p_temb, p_flag);
    // ---- CSR build ----
    k_scan1<<<NB, SB>>>(p_deg, p_off, p_bsum);
    k_scan2<<<1, 32>>>(p_bsum);
    k_scan3<<<(NN + TB - 1) / TB, TB>>>(p_off, p_bsum);
    k_fill<<<(EE + TB - 1) / TB, TB>>>(src, dst, p_off, p_cur, p_csr);

    // ---- layer 0 gather -> h0 ----
    k_gather<128><<<GGATH, TB>>>(p_y, p_off, p_csr, p_deg, b0, p_h0);

    // ---- layer 1 ----
    k_mma<128, 64, false, false><<<GB128, 128>>>(p_h0, p_wf + 1 * WFW, p_y, p_deg, 0, 0, 0);
    k_gather<64><<<GGATH, TB>>>(p_y, p_off, p_csr, p_deg, b1, p_h1);

    // ---- layer 2 ----
    k_mma<64, 128, false, false><<<GB64, 128>>>(p_h1, p_wf + 2 * WFW, p_y, p_deg, 0, 0, 0);
    k_gather<128><<<GGATH, TB>>>(p_y, p_off, p_csr, p_deg, b2, p_h2);

    // ---- layer 3: concat(h2,h0) @ w3 ----
    k_mma<128, 64, false, false><<<GB128, 128>>>(p_h2, p_wf + 3 * WFW, p_y, p_deg, 0, 0, 0);
    k_mma<128, 64, true,  false><<<GB128, 128>>>(p_h0, p_wf + 4 * WFW, p_y, p_deg, 0, 0, 0);
    k_gather<64><<<GGATH, TB>>>(p_y, p_off, p_csr, p_deg, b3, out);
}

// round 7
// speedup vs baseline: 1.5762x; 1.2165x over previous
#include <cuda_runtime.h>
#include <cuda_bf16.h>
#include <math.h>

#define NN 100000
#define EE 1000000
#define DD 64
#define GG 128
#define SB 512
#define NB ((NN + SB - 1) / SB)
#define WFW 8192   // words per weight-fragment matrix (FIN*FOUT bf16 hi+lo pairs)

// ---------------- scratch (device globals) -----------------------------------
__device__ int   g_deg[NN];
__device__ int   g_flag[NN];
__device__ float g_temb[DD];
__device__ float g_y[NN * GG];
__device__ float g_h0[NN * GG];
__device__ float g_h1[NN * (GG / 2)];
__device__ float g_h2[NN * GG];
__device__ int   g_off[NN + 1];
__device__ int   g_bsum[NB + 1];
__device__ int   g_cur[NN];
__device__ int   g_csr[EE];
__device__ unsigned g_wf[5 * WFW];

// ---------------- small kernels ---------------------------------------------
__global__ void k_init(int* deg, int* flag, int* cur) {
    int i = blockIdx.x * blockDim.x + threadIdx.x;
    if (i < NN) { deg[i] = 0; flag[i] = 0; cur[i] = 0; }
}

__global__ void k_deg(const int* __restrict__ dst, int* deg) {
    int e = blockIdx.x * blockDim.x + threadIdx.x;
    if (e < EE) atomicAdd(&deg[dst[e]], 1);
}

// ---------------- bf16 helpers ------------------------------------------------
__device__ __forceinline__ unsigned pack_bf16(float a, float b) {
    __nv_bfloat162 t = __floats2bfloat162_rn(a, b);
    return *(unsigned*)&t;
}
__device__ __forceinline__ void mma16(float* d, const unsigned* a, unsigned b0, unsigned b1) {
    asm volatile("mma.sync.aligned.m16n8k16.row.col.f32.bf16.bf16.f32 "
        "{%0,%1,%2,%3}, {%4,%5,%6,%7}, {%8,%9}, {%0,%1,%2,%3};"
        : "+f"(d[0]), "+f"(d[1]), "+f"(d[2]), "+f"(d[3])
        : "r"(a[0]), "r"(a[1]), "r"(a[2]), "r"(a[3]), "r"(b0), "r"(b1));
}

// ---------------- weight prep + temb + flag scatter ---------------------------
// blocks 0-4: weights -> bf16 hi/lo B-fragments; block 5: temb MLP; >=6: flags
__global__ void k_wprep(const float* __restrict__ w0, const float* __restrict__ w1,
                        const float* __restrict__ w2, const float* __restrict__ w3,
                        unsigned* __restrict__ wf,
                        const int* __restrict__ t,
                        const float* __restrict__ tw1, const float* __restrict__ tb1,
                        const float* __restrict__ tw2, const float* __restrict__ tb2,
                        float* __restrict__ temb,
                        const int* __restrict__ anm, int n_anm,
                        const int* __restrict__ nrm, int n_nrm, int* flag) {
    __shared__ float emb[DD];
    __shared__ float h[DD];
    int b = blockIdx.x;
    int tid = threadIdx.x;
    if (b >= 6) {
        int i = (b - 6) * 256 + tid;
        if (i < n_anm) atomicMax(&flag[anm[i]], 1);
        if (i < n_nrm) atomicMax(&flag[nrm[i]], 2);
        return;
    }
    if (b == 5) {
        if (tid < 32) {
            float tv = (float)t[0];
            float freq = expf((float)tid * (-logf(10000.0f) / 31.0f));
            float arg = tv * freq;
            emb[tid] = sinf(arg);
            emb[tid + 32] = cosf(arg);
        }
        __syncthreads();
        if (tid < DD) {
            float acc = tb1[tid];
            #pragma unroll
            for (int k = 0; k < DD; k++) acc += emb[k] * tw1[k * DD + tid];
            acc = acc / (1.0f + expf(-acc));
            h[tid] = acc;
        }
        __syncthreads();
        if (tid < DD) {
            float acc2 = tb2[tid];
            #pragma unroll
            for (int k = 0; k < DD; k++) acc2 += h[k] * tw2[k * DD + tid];
            temb[tid] = acc2;
        }
        return;
    }
    const float* Wg;
    int fout;
    switch (b) {
        case 0: Wg = w0; fout = 128; break;
        case 1: Wg = w1; fout = 64;  break;
        case 2: Wg = w2; fout = 128; break;
        case 3: Wg = w3; fout = 64;  break;
        default: Wg = w3 + 128 * 64; fout = 64; break;
    }
    uint4* out = (uint4*)(wf + b * WFW);
    const int total = WFW / 4;     // 2048 uint4 per matrix
    int jt = fout / 8;
    for (int p = tid; p < total; p += blockDim.x) {
        int ks = p / (jt * 32);
        int rem = p % (jt * 32);
        int j = rem / 32;
        int ln = rem % 32;
        int col = j * 8 + (ln >> 2);
        int k0 = ks * 16 + (ln & 3) * 2;
        float v0 = __ldg(&Wg[k0 * fout + col]);
        float v1 = __ldg(&Wg[(k0 + 1) * fout + col]);
        float v2 = __ldg(&Wg[(k0 + 8) * fout + col]);
        float v3 = __ldg(&Wg[(k0 + 9) * fout + col]);
        __nv_bfloat16 h0 = __float2bfloat16_rn(v0);
        __nv_bfloat16 h1 = __float2bfloat16_rn(v1);
        __nv_bfloat16 h2 = __float2bfloat16_rn(v2);
        __nv_bfloat16 h3 = __float2bfloat16_rn(v3);
        unsigned bh0 = pack_bf16(v0, v1);  // exact: pack uses rn of same values
        unsigned bh1 = pack_bf16(v2, v3);
        unsigned bl0 = pack_bf16(v0 - __bfloat162float(h0), v1 - __bfloat162float(h1));
        unsigned bl1 = pack_bf16(v2 - __bfloat162float(h2), v3 - __bfloat162float(h3));
        out[p] = make_uint4(bh0, bh1, bl0, bl1);
    }
}

// ---------------- CSR build --------------------------------------------------
__global__ void k_scan1(const int* __restrict__ deg, int* off, int* bsum) {
    __shared__ int sh[SB];
    int i = blockIdx.x * SB + threadIdx.x;
    int v = (i < NN) ? deg[i] : 0;
    sh[threadIdx.x] = v;
    __syncthreads();
    for (int s = 1; s < SB; s <<= 1) {
        int t = (threadIdx.x >= s) ? sh[threadIdx.x - s] : 0;
        __syncthreads();
        sh[threadIdx.x] += t;
        __syncthreads();
    }
    if (i < NN) off[i] = sh[threadIdx.x] - v;
    if (threadIdx.x == SB - 1) bsum[blockIdx.x] = sh[SB - 1];
}

__global__ void k_scan2(int* bsum) {
    if (threadIdx.x == 0) {
        int acc = 0;
        for (int b = 0; b < NB; b++) { int t = bsum[b]; bsum[b] = acc; acc += t; }
    }
}

__global__ void k_scan3(int* off, const int* __restrict__ bsum) {
    int i = blockIdx.x * blockDim.x + threadIdx.x;
    if (i < NN) off[i] += bsum[i / SB];
    if (i == 0) off[NN] = EE;
}

__global__ void k_fill(const int* __restrict__ src, const int* __restrict__ dst,
                       const int* __restrict__ off, int* cur, int* csr) {
    int e = blockIdx.x * blockDim.x + threadIdx.x;
    if (e < EE) {
        int d = dst[e];
        int p = off[d] + atomicAdd(&cur[d], 1);
        csr[p] = src[e];
    }
}

// ---------------- 3x bf16-split MMA GEMM --------------------------------------
// Y[r,c] (+)= (sum_k X[r,k]*W[k,c]) * rsqrt(deg[r]+1)
// 256 threads; warp tile 32x32; BM=64 (FOUT=128) or 128 (FOUT=64); BK=32.
template <int FIN, int FOUT, bool ACC, bool FUSE0>
__global__ void __launch_bounds__(256) k_mma(const float* __restrict__ X,
                                             const unsigned* __restrict__ WfG,
                                             float* __restrict__ Y,
                                             const int* __restrict__ deg,
                                             const float* __restrict__ lemb,
                                             const float* __restrict__ temb,
                                             const int* __restrict__ flag) {
    constexpr int BM = (FOUT == 128) ? 64 : 128;
    constexpr int BK = 32;
    constexpr int NJ = 4;                       // 4 n8-tiles = 32 cols per warp
    constexpr int NWX = FOUT / 32;              // warps along N
    constexpr int XROW = 36;                    // 16 hi + 16 lo words + 4 pad
    __shared__ unsigned Xs[BM * XROW];
    __shared__ float temb_s[DD], l0_s[DD], l1_s[DD];

    int tid = threadIdx.x;
    int lane = tid & 31, wid = tid >> 5;
    int wx = wid % NWX;
    int wy = wid / NWX;

    if (FUSE0 && tid < DD) {
        temb_s[tid] = temb[tid];
        l0_s[tid] = lemb[tid];
        l1_s[tid] = lemb[DD + tid];
    }

    int base = blockIdx.x * BM;
    float acc[2][NJ][4];
    #pragma unroll
    for (int mi = 0; mi < 2; mi++)
        #pragma unroll
        for (int j = 0; j < NJ; j++)
            #pragma unroll
            for (int q = 0; q < 4; q++) acc[mi][j][q] = 0.f;

    const uint4* Wf4 = (const uint4*)WfG;

    for (int kc = 0; kc < FIN; kc += BK) {
        __syncthreads();
        // stage X chunk [BM][BK] -> bf16 hi (words 0..15) + lo (words 16..31)
        for (int q = tid; q < BM * (BK / 4); q += 256) {
            int r = q / (BK / 4), qq = q % (BK / 4);
            int gr = base + r; if (gr >= NN) gr = NN - 1;
            float4 v = *(const float4*)&X[(size_t)gr * FIN + kc + qq * 4];
            float vv[4] = {v.x, v.y, v.z, v.w};
            if (FUSE0) {
                int fl = flag[gr];
                #pragma unroll
                for (int i = 0; i < 4; i++) {
                    int kk = kc + qq * 4 + i;
                    vv[i] += temb_s[kk];
                    if (fl == 1) vv[i] += l1_s[kk];
                    else if (fl == 2) vv[i] += l0_s[kk];
                }
            }
            __nv_bfloat16 h0 = __float2bfloat16_rn(vv[0]);
            __nv_bfloat16 h1 = __float2bfloat16_rn(vv[1]);
            __nv_bfloat16 h2 = __float2bfloat16_rn(vv[2]);
            __nv_bfloat16 h3 = __float2bfloat16_rn(vv[3]);
            unsigned* row = &Xs[r * XROW];
            row[qq * 2]          = pack_bf16(vv[0], vv[1]);
            row[qq * 2 + 1]      = pack_bf16(vv[2], vv[3]);
            row[16 + qq * 2]     = pack_bf16(vv[0] - __bfloat162float(h0),
                                             vv[1] - __bfloat162float(h1));
            row[16 + qq * 2 + 1] = pack_bf16(vv[2] - __bfloat162float(h2),
                                             vv[3] - __bfloat162float(h3));
        }
        __syncthreads();
        #pragma unroll
        for (int kl = 0; kl < BK; kl += 16) {
            int ksg = (kc + kl) >> 4;
            unsigned ah[2][4], al[2][4];
            #pragma unroll
            for (int mi = 0; mi < 2; mi++) {
                int r = wy * 32 + mi * 16 + (lane >> 2);
                int kp = (kl >> 1) + (lane & 3);
                const unsigned* rp0 = &Xs[r * XROW];
                const unsigned* rp1 = &Xs[(r + 8) * XROW];
                ah[mi][0] = rp0[kp];      ah[mi][1] = rp1[kp];
                ah[mi][2] = rp0[kp + 4];  ah[mi][3] = rp1[kp + 4];
                al[mi][0] = rp0[kp + 16]; al[mi][1] = rp1[kp + 16];
                al[mi][2] = rp0[kp + 20]; al[mi][3] = rp1[kp + 20];
            }
            #pragma unroll
            for (int j = 0; j < NJ; j++) {
                uint4 b = __ldg(&Wf4[(ksg * (FOUT / 8) + wx * NJ + j) * 32 + lane]);
                #pragma unroll
                for (int mi = 0; mi < 2; mi++) {
                    mma16(acc[mi][j], al[mi], b.x, b.y);   // al*bh
                    mma16(acc[mi][j], ah[mi], b.z, b.w);   // ah*bl
                    mma16(acc[mi][j], ah[mi], b.x, b.y);   // ah*bh
                }
            }
        }
    }

    int cb = wx * 32 + 2 * (lane & 3);
    #pragma unroll
    for (int mi = 0; mi < 2; mi++) {
        int r0 = base + wy * 32 + mi * 16 + (lane >> 2);
        int r1 = r0 + 8;
        float s0 = (r0 < NN) ? rsqrtf((float)deg[r0] + 1.0f) : 0.f;
        float s1 = (r1 < NN) ? rsqrtf((float)deg[r1] + 1.0f) : 0.f;
        #pragma unroll
        for (int j = 0; j < NJ; j++) {
            int c = cb + j * 8;
            if (r0 < NN) {
                float2* yp = (float2*)&Y[(size_t)r0 * FOUT + c];
                float2 o = make_float2(acc[mi][j][0] * s0, acc[mi][j][1] * s0);
                if (ACC) { float2 t = *yp; o.x += t.x; o.y += t.y; }
                *yp = o;
            }
            if (r1 < NN) {
                float2* yp = (float2*)&Y[(size_t)r1 * FOUT + c];
                float2 o = make_float2(acc[mi][j][2] * s1, acc[mi][j][3] * s1);
                if (ACC) { float2 t = *yp; o.x += t.x; o.y += t.y; }
                *yp = o;
            }
        }
    }
}

// ---------------- gather: out = silu(dinv*(sum_in y[src] + y[i]) + b) --------
template <int F>
__global__ void __launch_bounds__(256) k_gather(const float* __restrict__ y,
                                                const int* __restrict__ off,
                                                const int* __restrict__ csr,
                                                const int* __restrict__ deg,
                                                const float* __restrict__ b,
                                                float* __restrict__ out) {
    int warp = (blockIdx.x * 256 + threadIdx.x) >> 5;
    int lane = threadIdx.x & 31;
    if (warp >= NN) return;
    int beg = off[warp], end = off[warp + 1];
    constexpr int V = F / 32;
    float acc[V];
    {
        const float* yr = y + (size_t)warp * F + lane * V;
        if constexpr (V == 4) {
            float4 t = *(const float4*)yr;
            acc[0] = t.x; acc[1] = t.y; acc[2] = t.z; acc[3] = t.w;
        } else {
            float2 t = *(const float2*)yr;
            acc[0] = t.x; acc[1] = t.y;
        }
    }
    for (int eb = beg; eb < end; eb += 32) {
        int n = end - eb; if (n > 32) n = 32;
        int s = (lane < n) ? __ldg(&csr[eb + lane]) : 0;
        int j = 0;
        for (; j + 4 <= n; j += 4) {
            int s0 = __shfl_sync(0xffffffffu, s, j);
            int s1 = __shfl_sync(0xffffffffu, s, j + 1);
            int s2 = __shfl_sync(0xffffffffu, s, j + 2);
            int s3 = __shfl_sync(0xffffffffu, s, j + 3);
            if constexpr (V == 4) {
                float4 t0 = *(const float4*)(y + (size_t)s0 * F + lane * 4);
                float4 t1 = *(const float4*)(y + (size_t)s1 * F + lane * 4);
                float4 t2 = *(const float4*)(y + (size_t)s2 * F + lane * 4);
                float4 t3 = *(const float4*)(y + (size_t)s3 * F + lane * 4);
                acc[0] += (t0.x + t1.x) + (t2.x + t3.x);
                acc[1] += (t0.y + t1.y) + (t2.y + t3.y);
                acc[2] += (t0.z + t1.z) + (t2.z + t3.z);
                acc[3] += (t0.w + t1.w) + (t2.w + t3.w);
            } else {
                float2 t0 = *(const float2*)(y + (size_t)s0 * F + lane * 2);
                float2 t1 = *(const float2*)(y + (size_t)s1 * F + lane * 2);
                float2 t2 = *(const float2*)(y + (size_t)s2 * F + lane * 2);
                float2 t3 = *(const float2*)(y + (size_t)s3 * F + lane * 2);
                acc[0] += (t0.x + t1.x) + (t2.x + t3.x);
                acc[1] += (t0.y + t1.y) + (t2.y + t3.y);
            }
        }
        for (; j < n; j++) {
            int sj = __shfl_sync(0xffffffffu, s, j);
            const float* yr = y + (size_t)sj * F + lane * V;
            if constexpr (V == 4) {
                float4 t = *(const float4*)yr;
                acc[0] += t.x; acc[1] += t.y; acc[2] += t.z; acc[3] += t.w;
            } else {
                float2 t = *(const float2*)yr;
                acc[0] += t.x; acc[1] += t.y;
            }
        }
    }
    float di = rsqrtf((float)deg[warp] + 1.0f);
    float ov[V];
    #pragma unroll
    for (int v = 0; v < V; v++) {
        float val = di * acc[v] + b[lane * V + v];
        ov[v] = val / (1.0f + expf(-val));
    }
    float* op = out + (size_t)warp * F + lane * V;
    if constexpr (V == 4) *(float4*)op = make_float4(ov[0], ov[1], ov[2], ov[3]);
    else *(float2*)op = make_float2(ov[0], ov[1]);
}

// ---------------- launch ----------------------------------------------------
extern "C" void kernel_launch(void* const* d_in, const int* in_sizes, int n_in,
                              void* d_out, int out_size) {
    const float* noise_x   = (const float*)d_in[0];
    const int*   edge      = (const int*)d_in[1];
    const int*   t_in      = (const int*)d_in[2];
    const int*   train_anm = (const int*)d_in[3];
    const int*   train_nrm = (const int*)d_in[4];
    const float* time_w1   = (const float*)d_in[5];
    const float* time_b1   = (const float*)d_in[6];
    const float* time_w2   = (const float*)d_in[7];
    const float* time_b2   = (const float*)d_in[8];
    const float* label_emb = (const float*)d_in[9];
    const float* w0 = (const float*)d_in[10];
    const float* b0 = (const float*)d_in[11];
    const float* w1 = (const float*)d_in[12];
    const float* b1 = (const float*)d_in[13];
    const float* w2 = (const float*)d_in[14];
    const float* b2 = (const float*)d_in[15];
    const float* w3 = (const float*)d_in[16];
    const float* b3 = (const float*)d_in[17];
    float* out = (float*)d_out;

    const int* src = edge;
    const int* dst = edge + EE;
    int n_anm = in_sizes[3];
    int n_nrm = in_sizes[4];
    int n_fl = (n_anm > n_nrm) ? n_anm : n_nrm;

    float *p_temb, *p_y, *p_h0, *p_h1, *p_h2;
    int *p_deg, *p_flag, *p_off, *p_bsum, *p_cur, *p_csr;
    unsigned *p_wf;
    cudaGetSymbolAddress((void**)&p_temb, g_temb);
    cudaGetSymbolAddress((void**)&p_y,    g_y);
    cudaGetSymbolAddress((void**)&p_h0,   g_h0);
    cudaGetSymbolAddress((void**)&p_h1,   g_h1);
    cudaGetSymbolAddress((void**)&p_h2,   g_h2);
    cudaGetSymbolAddress((void**)&p_deg,  g_deg);
    cudaGetSymbolAddress((void**)&p_flag, g_flag);
    cudaGetSymbolAddress((void**)&p_off,  g_off);
    cudaGetSymbolAddress((void**)&p_bsum, g_bsum);
    cudaGetSymbolAddress((void**)&p_cur,  g_cur);
    cudaGetSymbolAddress((void**)&p_csr,  g_csr);
    cudaGetSymbolAddress((void**)&p_wf,   g_wf);

    const int TB = 256;
    const int GB64  = (NN + 63) / 64;
    const int GB128 = (NN + 127) / 128;
    const int GGATH = (NN * 32 + TB - 1) / TB;

    // 0 init, 1 deg, 2 wprep(+temb+flags), 3 gemm0  <- profiler captures idx 3
    k_init<<<(NN + TB - 1) / TB, TB>>>(p_deg, p_flag, p_cur);
    k_deg<<<(EE + TB - 1) / TB, TB>>>(dst, p_deg);
    k_wprep<<<6 + (n_fl + 255) / 256, 256>>>(w0, w1, w2, w3, p_wf,
                        t_in, time_w1, time_b1, time_w2, time_b2, p_temb,
                        train_anm, n_anm, train_nrm, n_nrm, p_flag);
    k_mma<64, 128, false, true><<<GB64, 256>>>(noise_x, p_wf + 0 * WFW, p_y, p_deg,
                                               label_emb, p_temb, p_flag);
    // ---- CSR build ----
    k_scan1<<<NB, SB>>>(p_deg, p_off, p_bsum);
    k_scan2<<<1, 32>>>(p_bsum);
    k_scan3<<<(NN + TB - 1) / TB, TB>>>(p_off, p_bsum);
    k_fill<<<(EE + TB - 1) / TB, TB>>>(src, dst, p_off, p_cur, p_csr);

    // ---- layer 0 gather -> h0 ----
    k_gather<128><<<GGATH, TB>>>(p_y, p_off, p_csr, p_deg, b0, p_h0);

    // ---- layer 1 ----
    k_mma<128, 64, false, false><<<GB128, 256>>>(p_h0, p_wf + 1 * WFW, p_y, p_deg, 0, 0, 0);
    k_gather<64><<<GGATH, TB>>>(p_y, p_off, p_csr, p_deg, b1, p_h1);

    // ---- layer 2 ----
    k_mma<64, 128, false, false><<<GB64, 256>>>(p_h1, p_wf + 2 * WFW, p_y, p_deg, 0, 0, 0);
    k_gather<128><<<GGATH, TB>>>(p_y, p_off, p_csr, p_deg, b2, p_h2);

    // ---- layer 3: concat(h2,h0) @ w3 ----
    k_mma<128, 64, false, false><<<GB128, 256>>>(p_h2, p_wf + 3 * WFW, p_y, p_deg, 0, 0, 0);
    k_mma<128, 64, true,  false><<<GB128, 256>>>(p_h0, p_wf + 4 * WFW, p_y, p_deg, 0, 0, 0);
    k_gather<64><<<GGATH, TB>>>(p_y, p_off, p_csr, p_deg, b3, out);
}

// round 8
// speedup vs baseline: 1.7807x; 1.1297x over previous
#include <cuda_runtime.h>
#include <cuda_bf16.h>
#include <math.h>

#define NN 100000
#define EE 1000000
#define DD 64
#define GG 128
#define SB 512
#define NB ((NN + SB - 1) / SB)
#define WFW 8192   // words per weight-fragment matrix (bf16 hi/lo pairs)

// ---------------- scratch (device globals) -----------------------------------
__device__ int   g_deg[NN];
__device__ int   g_flag[NN];
__device__ float g_temb[DD];
__device__ float g_ab[NN * GG];    // two N x 64 ping-pong halves (A | B)
__device__ float g_h0[NN * GG];
__device__ float g_h2[NN * GG];
__device__ int   g_off[NN + 1];
__device__ int   g_bsum[NB + 1];
__device__ int   g_cur[NN];
__device__ int   g_csr[EE];
__device__ unsigned g_wf[5 * WFW];

// ---------------- small kernels ---------------------------------------------
__global__ void k_init(int* deg, int* flag, int* cur) {
    int i = blockIdx.x * blockDim.x + threadIdx.x;
    if (i < NN) { deg[i] = 0; flag[i] = 0; cur[i] = 0; }
}

__global__ void k_deg(const int* __restrict__ dst, int* deg) {
    int e = blockIdx.x * blockDim.x + threadIdx.x;
    if (e < EE) atomicAdd(&deg[dst[e]], 1);
}

// ---------------- bf16 helpers ------------------------------------------------
__device__ __forceinline__ unsigned pack_bf16(float a, float b) {
    __nv_bfloat162 t = __floats2bfloat162_rn(a, b);
    return *(unsigned*)&t;
}
__device__ __forceinline__ void mma16(float* d, const unsigned* a, unsigned b0, unsigned b1) {
    asm volatile("mma.sync.aligned.m16n8k16.row.col.f32.bf16.bf16.f32 "
        "{%0,%1,%2,%3}, {%4,%5,%6,%7}, {%8,%9}, {%0,%1,%2,%3};"
        : "+f"(d[0]), "+f"(d[1]), "+f"(d[2]), "+f"(d[3])
        : "r"(a[0]), "r"(a[1]), "r"(a[2]), "r"(a[3]), "r"(b0), "r"(b1));
}

// ---------------- weight prep + temb + flag scatter ---------------------------
__global__ void k_wprep(const float* __restrict__ w0, const float* __restrict__ w1,
                        const float* __restrict__ w2, const float* __restrict__ w3,
                        unsigned* __restrict__ wf,
                        const int* __restrict__ t,
                        const float* __restrict__ tw1, const float* __restrict__ tb1,
                        const float* __restrict__ tw2, const float* __restrict__ tb2,
                        float* __restrict__ temb,
                        const int* __restrict__ anm, int n_anm,
                        const int* __restrict__ nrm, int n_nrm, int* flag) {
    __shared__ float emb[DD];
    __shared__ float h[DD];
    int b = blockIdx.x;
    int tid = threadIdx.x;
    if (b >= 6) {
        int i = (b - 6) * 256 + tid;
        if (i < n_anm) atomicMax(&flag[anm[i]], 1);
        if (i < n_nrm) atomicMax(&flag[nrm[i]], 2);
        return;
    }
    if (b == 5) {
        if (tid < 32) {
            float tv = (float)t[0];
            float freq = expf((float)tid * (-logf(10000.0f) / 31.0f));
            float arg = tv * freq;
            emb[tid] = sinf(arg);
            emb[tid + 32] = cosf(arg);
        }
        __syncthreads();
        if (tid < DD) {
            float acc = tb1[tid];
            #pragma unroll
            for (int k = 0; k < DD; k++) acc += emb[k] * tw1[k * DD + tid];
            acc = acc / (1.0f + expf(-acc));
            h[tid] = acc;
        }
        __syncthreads();
        if (tid < DD) {
            float acc2 = tb2[tid];
            #pragma unroll
            for (int k = 0; k < DD; k++) acc2 += h[k] * tw2[k * DD + tid];
            temb[tid] = acc2;
        }
        return;
    }
    const float* Wg;
    int fout;
    switch (b) {
        case 0: Wg = w0; fout = 128; break;
        case 1: Wg = w1; fout = 64;  break;
        case 2: Wg = w2; fout = 128; break;
        case 3: Wg = w3; fout = 64;  break;
        default: Wg = w3 + 128 * 64; fout = 64; break;
    }
    uint4* out = (uint4*)(wf + b * WFW);
    const int total = WFW / 4;
    int jt = fout / 8;
    for (int p = tid; p < total; p += blockDim.x) {
        int ks = p / (jt * 32);
        int rem = p % (jt * 32);
        int j = rem / 32;
        int ln = rem % 32;
        int col = j * 8 + (ln >> 2);
        int k0 = ks * 16 + (ln & 3) * 2;
        float v0 = __ldg(&Wg[k0 * fout + col]);
        float v1 = __ldg(&Wg[(k0 + 1) * fout + col]);
        float v2 = __ldg(&Wg[(k0 + 8) * fout + col]);
        float v3 = __ldg(&Wg[(k0 + 9) * fout + col]);
        __nv_bfloat16 h0 = __float2bfloat16_rn(v0);
        __nv_bfloat16 h1 = __float2bfloat16_rn(v1);
        __nv_bfloat16 h2 = __float2bfloat16_rn(v2);
        __nv_bfloat16 h3 = __float2bfloat16_rn(v3);
        unsigned bh0 = pack_bf16(v0, v1);
        unsigned bh1 = pack_bf16(v2, v3);
        unsigned bl0 = pack_bf16(v0 - __bfloat162float(h0), v1 - __bfloat162float(h1));
        unsigned bl1 = pack_bf16(v2 - __bfloat162float(h2), v3 - __bfloat162float(h3));
        out[p] = make_uint4(bh0, bh1, bl0, bl1);
    }
}

// ---------------- z0 = (noise + temb + label) * dinv --------------------------
__global__ void k_z0(const float* __restrict__ noise,
                     const float* __restrict__ lemb,
                     const float* __restrict__ temb,
                     const int* __restrict__ flag,
                     const int* __restrict__ deg,
                     float* __restrict__ z) {
    int idx = blockIdx.x * blockDim.x + threadIdx.x;
    if (idx >= NN * (DD / 4)) return;
    int node = idx >> 4;
    int f4 = idx & 15;
    float4 v = ((const float4*)noise)[idx];
    float4 tb = ((const float4*)temb)[f4];
    v.x += tb.x; v.y += tb.y; v.z += tb.z; v.w += tb.w;
    int fl = flag[node];
    if (fl == 1) {
        float4 l = ((const float4*)(lemb + DD))[f4];
        v.x += l.x; v.y += l.y; v.z += l.z; v.w += l.w;
    } else if (fl == 2) {
        float4 l = ((const float4*)lemb)[f4];
        v.x += l.x; v.y += l.y; v.z += l.z; v.w += l.w;
    }
    float di = rsqrtf((float)deg[node] + 1.0f);
    v.x *= di; v.y *= di; v.z *= di; v.w *= di;
    ((float4*)z)[idx] = v;
}

// ---------------- CSR build --------------------------------------------------
__global__ void k_scan1(const int* __restrict__ deg, int* off, int* bsum) {
    __shared__ int sh[SB];
    int i = blockIdx.x * SB + threadIdx.x;
    int v = (i < NN) ? deg[i] : 0;
    sh[threadIdx.x] = v;
    __syncthreads();
    for (int s = 1; s < SB; s <<= 1) {
        int t = (threadIdx.x >= s) ? sh[threadIdx.x - s] : 0;
        __syncthreads();
        sh[threadIdx.x] += t;
        __syncthreads();
    }
    if (i < NN) off[i] = sh[threadIdx.x] - v;
    if (threadIdx.x == SB - 1) bsum[blockIdx.x] = sh[SB - 1];
}

__global__ void k_scan2(int* bsum) {
    if (threadIdx.x == 0) {
        int acc = 0;
        for (int b = 0; b < NB; b++) { int t = bsum[b]; bsum[b] = acc; acc += t; }
    }
}

__global__ void k_scan3(int* off, const int* __restrict__ bsum) {
    int i = blockIdx.x * blockDim.x + threadIdx.x;
    if (i < NN) off[i] += bsum[i / SB];
    if (i == 0) off[NN] = EE;
}

__global__ void k_fill(const int* __restrict__ src, const int* __restrict__ dst,
                       const int* __restrict__ off, int* cur, int* csr) {
    int e = blockIdx.x * blockDim.x + threadIdx.x;
    if (e < EE) {
        int d = dst[e];
        int p = off[d] + atomicAdd(&cur[d], 1);
        csr[p] = src[e];
    }
}

// ---------------- 3x bf16-split MMA GEMM --------------------------------------
// EPI 0: Y = acc * dinv (optionally += existing Y when ACC)
// EPI 1: Y = silu(acc + bias)
template <int FIN, int FOUT, bool ACC, int EPI>
__global__ void __launch_bounds__(256) k_mma(const float* __restrict__ X,
                                             const unsigned* __restrict__ WfG,
                                             float* __restrict__ Y,
                                             const int* __restrict__ deg,
                                             const float* __restrict__ bias) {
    constexpr int BM = (FOUT == 128) ? 64 : 128;
    constexpr int BK = 32;
    constexpr int NJ = 4;
    constexpr int NWX = FOUT / 32;
    constexpr int XROW = 36;
    __shared__ unsigned Xs[BM * XROW];

    int tid = threadIdx.x;
    int lane = tid & 31, wid = tid >> 5;
    int wx = wid % NWX;
    int wy = wid / NWX;

    int base = blockIdx.x * BM;
    float acc[2][NJ][4];
    #pragma unroll
    for (int mi = 0; mi < 2; mi++)
        #pragma unroll
        for (int j = 0; j < NJ; j++)
            #pragma unroll
            for (int q = 0; q < 4; q++) acc[mi][j][q] = 0.f;

    const uint4* Wf4 = (const uint4*)WfG;

    for (int kc = 0; kc < FIN; kc += BK) {
        __syncthreads();
        for (int q = tid; q < BM * (BK / 4); q += 256) {
            int r = q / (BK / 4), qq = q % (BK / 4);
            int gr = base + r; if (gr >= NN) gr = NN - 1;
            float4 v = *(const float4*)&X[(size_t)gr * FIN + kc + qq * 4];
            __nv_bfloat16 h0 = __float2bfloat16_rn(v.x);
            __nv_bfloat16 h1 = __float2bfloat16_rn(v.y);
            __nv_bfloat16 h2 = __float2bfloat16_rn(v.z);
            __nv_bfloat16 h3 = __float2bfloat16_rn(v.w);
            unsigned* row = &Xs[r * XROW];
            row[qq * 2]          = pack_bf16(v.x, v.y);
            row[qq * 2 + 1]      = pack_bf16(v.z, v.w);
            row[16 + qq * 2]     = pack_bf16(v.x - __bfloat162float(h0),
                                             v.y - __bfloat162float(h1));
            row[16 + qq * 2 + 1] = pack_bf16(v.z - __bfloat162float(h2),
                                             v.w - __bfloat162float(h3));
        }
        __syncthreads();
        #pragma unroll
        for (int kl = 0; kl < BK; kl += 16) {
            int ksg = (kc + kl) >> 4;
            unsigned ah[2][4], al[2][4];
            #pragma unroll
            for (int mi = 0; mi < 2; mi++) {
                int r = wy * 32 + mi * 16 + (lane >> 2);
                int kp = (kl >> 1) + (lane & 3);
                const unsigned* rp0 = &Xs[r * XROW];
                const unsigned* rp1 = &Xs[(r + 8) * XROW];
                ah[mi][0] = rp0[kp];      ah[mi][1] = rp1[kp];
                ah[mi][2] = rp0[kp + 4];  ah[mi][3] = rp1[kp + 4];
                al[mi][0] = rp0[kp + 16]; al[mi][1] = rp1[kp + 16];
                al[mi][2] = rp0[kp + 20]; al[mi][3] = rp1[kp + 20];
            }
            #pragma unroll
            for (int j = 0; j < NJ; j++) {
                uint4 b = __ldg(&Wf4[(ksg * (FOUT / 8) + wx * NJ + j) * 32 + lane]);
                #pragma unroll
                for (int mi = 0; mi < 2; mi++) {
                    mma16(acc[mi][j], al[mi], b.x, b.y);
                    mma16(acc[mi][j], ah[mi], b.z, b.w);
                    mma16(acc[mi][j], ah[mi], b.x, b.y);
                }
            }
        }
    }

    int cb = wx * 32 + 2 * (lane & 3);
    #pragma unroll
    for (int mi = 0; mi < 2; mi++) {
        int r0 = base + wy * 32 + mi * 16 + (lane >> 2);
        int r1 = r0 + 8;
        float s0 = 0.f, s1 = 0.f;
        if (EPI == 0) {
            s0 = (r0 < NN) ? rsqrtf((float)deg[r0] + 1.0f) : 0.f;
            s1 = (r1 < NN) ? rsqrtf((float)deg[r1] + 1.0f) : 0.f;
        }
        #pragma unroll
        for (int j = 0; j < NJ; j++) {
            int c = cb + j * 8;
            float bx = 0.f, by = 0.f;
            if (EPI == 1) { bx = __ldg(&bias[c]); by = __ldg(&bias[c + 1]); }
            if (r0 < NN) {
                float2* yp = (float2*)&Y[(size_t)r0 * FOUT + c];
                float2 o;
                if (EPI == 0) {
                    o = make_float2(acc[mi][j][0] * s0, acc[mi][j][1] * s0);
                    if (ACC) { float2 t = *yp; o.x += t.x; o.y += t.y; }
                } else {
                    float v0 = acc[mi][j][0] + bx;
                    float v1 = acc[mi][j][1] + by;
                    o = make_float2(v0 / (1.0f + expf(-v0)), v1 / (1.0f + expf(-v1)));
                }
                *yp = o;
            }
            if (r1 < NN) {
                float2* yp = (float2*)&Y[(size_t)r1 * FOUT + c];
                float2 o;
                if (EPI == 0) {
                    o = make_float2(acc[mi][j][2] * s1, acc[mi][j][3] * s1);
                    if (ACC) { float2 t = *yp; o.x += t.x; o.y += t.y; }
                } else {
                    float v2 = acc[mi][j][2] + bx;
                    float v3 = acc[mi][j][3] + by;
                    o = make_float2(v2 / (1.0f + expf(-v2)), v3 / (1.0f + expf(-v3)));
                }
                *yp = o;
            }
        }
    }
}

// ---------------- 64-wide gather ----------------------------------------------
// MODE 0 (pre):         out = dinv*(sum z[src] + z[i])
// MODE 1 (post):        out = silu(dinv*(sum y[src] + y[i]) + b)
// MODE 2 (post+scale):  out = silu(dinv*(sum y[src] + y[i]) + b) * dinv
template <int MODE>
__global__ void __launch_bounds__(256) k_gather64(const float* __restrict__ y,
                                                  const int* __restrict__ off,
                                                  const int* __restrict__ csr,
                                                  const int* __restrict__ deg,
                                                  const float* __restrict__ b,
                                                  float* __restrict__ out) {
    int warp = (blockIdx.x * 256 + threadIdx.x) >> 5;
    int lane = threadIdx.x & 31;
    if (warp >= NN) return;
    int beg = off[warp], end = off[warp + 1];
    float a0, a1;
    {
        float2 t = *(const float2*)(y + (size_t)warp * DD + lane * 2);
        a0 = t.x; a1 = t.y;
    }
    for (int eb = beg; eb < end; eb += 32) {
        int n = end - eb; if (n > 32) n = 32;
        int s = (lane < n) ? __ldg(&csr[eb + lane]) : 0;
        int j = 0;
        for (; j + 4 <= n; j += 4) {
            int s0 = __shfl_sync(0xffffffffu, s, j);
            int s1 = __shfl_sync(0xffffffffu, s, j + 1);
            int s2 = __shfl_sync(0xffffffffu, s, j + 2);
            int s3 = __shfl_sync(0xffffffffu, s, j + 3);
            float2 t0 = *(const float2*)(y + (size_t)s0 * DD + lane * 2);
            float2 t1 = *(const float2*)(y + (size_t)s1 * DD + lane * 2);
            float2 t2 = *(const float2*)(y + (size_t)s2 * DD + lane * 2);
            float2 t3 = *(const float2*)(y + (size_t)s3 * DD + lane * 2);
            a0 += (t0.x + t1.x) + (t2.x + t3.x);
            a1 += (t0.y + t1.y) + (t2.y + t3.y);
        }
        for (; j < n; j++) {
            int sj = __shfl_sync(0xffffffffu, s, j);
            float2 t = *(const float2*)(y + (size_t)sj * DD + lane * 2);
            a0 += t.x; a1 += t.y;
        }
    }
    float di = rsqrtf((float)deg[warp] + 1.0f);
    float o0, o1;
    if (MODE == 0) {
        o0 = di * a0; o1 = di * a1;
    } else {
        float v0 = di * a0 + b[lane * 2];
        float v1 = di * a1 + b[lane * 2 + 1];
        o0 = v0 / (1.0f + expf(-v0));
        o1 = v1 / (1.0f + expf(-v1));
        if (MODE == 2) { o0 *= di; o1 *= di; }
    }
    *(float2*)(out + (size_t)warp * DD + lane * 2) = make_float2(o0, o1);
}

// ---------------- launch ----------------------------------------------------
extern "C" void kernel_launch(void* const* d_in, const int* in_sizes, int n_in,
                              void* d_out, int out_size) {
    const float* noise_x   = (const float*)d_in[0];
    const int*   edge      = (const int*)d_in[1];
    const int*   t_in      = (const int*)d_in[2];
    const int*   train_anm = (const int*)d_in[3];
    const int*   train_nrm = (const int*)d_in[4];
    const float* time_w1   = (const float*)d_in[5];
    const float* time_b1   = (const float*)d_in[6];
    const float* time_w2   = (const float*)d_in[7];
    const float* time_b2   = (const float*)d_in[8];
    const float* label_emb = (const float*)d_in[9];
    const float* w0 = (const float*)d_in[10];
    const float* b0 = (const float*)d_in[11];
    const float* w1 = (const float*)d_in[12];
    const float* b1 = (const float*)d_in[13];
    const float* w2 = (const float*)d_in[14];
    const float* b2 = (const float*)d_in[15];
    const float* w3 = (const float*)d_in[16];
    const float* b3 = (const float*)d_in[17];
    float* out = (float*)d_out;

    const int* src = edge;
    const int* dst = edge + EE;
    int n_anm = in_sizes[3];
    int n_nrm = in_sizes[4];
    int n_fl = (n_anm > n_nrm) ? n_anm : n_nrm;

    float *p_temb, *p_ab, *p_h0, *p_h2;
    int *p_deg, *p_flag, *p_off, *p_bsum, *p_cur, *p_csr;
    unsigned *p_wf;
    cudaGetSymbolAddress((void**)&p_temb, g_temb);
    cudaGetSymbolAddress((void**)&p_ab,   g_ab);
    cudaGetSymbolAddress((void**)&p_h0,   g_h0);
    cudaGetSymbolAddress((void**)&p_h2,   g_h2);
    cudaGetSymbolAddress((void**)&p_deg,  g_deg);
    cudaGetSymbolAddress((void**)&p_flag, g_flag);
    cudaGetSymbolAddress((void**)&p_off,  g_off);
    cudaGetSymbolAddress((void**)&p_bsum, g_bsum);
    cudaGetSymbolAddress((void**)&p_cur,  g_cur);
    cudaGetSymbolAddress((void**)&p_csr,  g_csr);
    cudaGetSymbolAddress((void**)&p_wf,   g_wf);

    float* A = p_ab;                 // N x 64
    float* B = p_ab + (size_t)NN * DD;

    const int TB = 256;
    const int GB64  = (NN + 63) / 64;      // FOUT=128 tiles (BM=64)
    const int GB128 = (NN + 127) / 128;    // FOUT=64 tiles (BM=128)
    const int GGATH = (NN * 32 + TB - 1) / TB;

    k_init<<<(NN + TB - 1) / TB, TB>>>(p_deg, p_flag, p_cur);
    k_deg<<<(EE + TB - 1) / TB, TB>>>(dst, p_deg);
    k_wprep<<<6 + (n_fl + 255) / 256, 256>>>(w0, w1, w2, w3, p_wf,
                        t_in, time_w1, time_b1, time_w2, time_b2, p_temb,
                        train_anm, n_anm, train_nrm, n_nrm, p_flag);
    k_z0<<<(NN * 16 + TB - 1) / TB, TB>>>(noise_x, label_emb, p_temb, p_flag, p_deg, A);

    // ---- CSR build ----
    k_scan1<<<NB, SB>>>(p_deg, p_off, p_bsum);
    k_scan2<<<1, 32>>>(p_bsum);
    k_scan3<<<(NN + TB - 1) / TB, TB>>>(p_off, p_bsum);
    k_fill<<<(EE + TB - 1) / TB, TB>>>(src, dst, p_off, p_cur, p_csr);

    // ---- layer 0: aggregate-before ----
    k_gather64<0><<<GGATH, TB>>>(A, p_off, p_csr, p_deg, 0, B);           // g0
    k_mma<64, 128, false, 1><<<GB64, 256>>>(B, p_wf + 0 * WFW, p_h0, p_deg, b0);

    // ---- layer 1: aggregate-after ----
    k_mma<128, 64, false, 0><<<GB128, 256>>>(p_h0, p_wf + 1 * WFW, A, p_deg, 0);
    k_gather64<2><<<GGATH, TB>>>(A, p_off, p_csr, p_deg, b1, B);          // z2 = h1*dinv

    // ---- layer 2: aggregate-before ----
    k_gather64<0><<<GGATH, TB>>>(B, p_off, p_csr, p_deg, 0, A);           // g2
    k_mma<64, 128, false, 1><<<GB64, 256>>>(A, p_wf + 2 * WFW, p_h2, p_deg, b2);

    // ---- layer 3: concat(h2,h0), aggregate-after ----
    k_mma<128, 64, false, 0><<<GB128, 256>>>(p_h2, p_wf + 3 * WFW, B, p_deg, 0);
    k_mma<128, 64, true,  0><<<GB128, 256>>>(p_h0, p_wf + 4 * WFW, B, p_deg, 0);
    k_gather64<1><<<GGATH, TB>>>(B, p_off, p_csr, p_deg, b3, out);
}

// round 9
// speedup vs baseline: 2.0254x; 1.1374x over previous
#include <cuda_runtime.h>
#include <cuda_bf16.h>
#include <math.h>

#define NN 100000
#define EE 1000000
#define DD 64
#define GG 128
#define SB 512
#define NB ((NN + SB - 1) / SB)
#define WFW 8192   // words per weight-fragment matrix (bf16 hi/lo pairs)

// ---------------- scratch (device globals) -----------------------------------
__device__ int   g_deg[NN];
__device__ int   g_flag[NN];
__device__ float g_temb[DD];
__device__ float g_ab[NN * GG];    // two N x 64 ping-pong halves (A | B)
__device__ float g_h0[NN * GG];
__device__ float g_h2[NN * GG];
__device__ int   g_off[NN + 1];
__device__ int   g_bsum[NB + 1];
__device__ int   g_cur[NN];
__device__ int   g_csr[EE];
__device__ unsigned g_wf[5 * WFW];

// ---------------- small kernels ---------------------------------------------
__global__ void k_init(int* deg, int* flag, int* cur) {
    int i = blockIdx.x * blockDim.x + threadIdx.x;
    if (i < NN) { deg[i] = 0; flag[i] = 0; cur[i] = 0; }
}

__global__ void k_deg(const int* __restrict__ dst, int* deg) {
    int e = blockIdx.x * blockDim.x + threadIdx.x;
    if (e < EE) atomicAdd(&deg[dst[e]], 1);
}

// ---------------- bf16 helpers ------------------------------------------------
__device__ __forceinline__ unsigned pack_bf16(float a, float b) {
    __nv_bfloat162 t = __floats2bfloat162_rn(a, b);
    return *(unsigned*)&t;
}
__device__ __forceinline__ void mma16(float* d, const unsigned* a, unsigned b0, unsigned b1) {
    asm volatile("mma.sync.aligned.m16n8k16.row.col.f32.bf16.bf16.f32 "
        "{%0,%1,%2,%3}, {%4,%5,%6,%7}, {%8,%9}, {%0,%1,%2,%3};"
        : "+f"(d[0]), "+f"(d[1]), "+f"(d[2]), "+f"(d[3])
        : "r"(a[0]), "r"(a[1]), "r"(a[2]), "r"(a[3]), "r"(b0), "r"(b1));
}

// ---------------- weight prep + temb + flag scatter ---------------------------
__global__ void k_wprep(const float* __restrict__ w0, const float* __restrict__ w1,
                        const float* __restrict__ w2, const float* __restrict__ w3,
                        unsigned* __restrict__ wf,
                        const int* __restrict__ t,
                        const float* __restrict__ tw1, const float* __restrict__ tb1,
                        const float* __restrict__ tw2, const float* __restrict__ tb2,
                        float* __restrict__ temb,
                        const int* __restrict__ anm, int n_anm,
                        const int* __restrict__ nrm, int n_nrm, int* flag) {
    __shared__ float emb[DD];
    __shared__ float h[DD];
    int b = blockIdx.x;
    int tid = threadIdx.x;
    if (b >= 6) {
        int i = (b - 6) * 256 + tid;
        if (i < n_anm) atomicMax(&flag[anm[i]], 1);
        if (i < n_nrm) atomicMax(&flag[nrm[i]], 2);
        return;
    }
    if (b == 5) {
        if (tid < 32) {
            float tv = (float)t[0];
            float freq = expf((float)tid * (-logf(10000.0f) / 31.0f));
            float arg = tv * freq;
            emb[tid] = sinf(arg);
            emb[tid + 32] = cosf(arg);
        }
        __syncthreads();
        if (tid < DD) {
            float acc = tb1[tid];
            #pragma unroll
            for (int k = 0; k < DD; k++) acc += emb[k] * tw1[k * DD + tid];
            acc = acc / (1.0f + expf(-acc));
            h[tid] = acc;
        }
        __syncthreads();
        if (tid < DD) {
            float acc2 = tb2[tid];
            #pragma unroll
            for (int k = 0; k < DD; k++) acc2 += h[k] * tw2[k * DD + tid];
            temb[tid] = acc2;
        }
        return;
    }
    const float* Wg;
    int fout;
    switch (b) {
        case 0: Wg = w0; fout = 128; break;
        case 1: Wg = w1; fout = 64;  break;
        case 2: Wg = w2; fout = 128; break;
        case 3: Wg = w3; fout = 64;  break;
        default: Wg = w3 + 128 * 64; fout = 64; break;
    }
    uint4* out = (uint4*)(wf + b * WFW);
    const int total = WFW / 4;
    int jt = fout / 8;
    for (int p = tid; p < total; p += blockDim.x) {
        int ks = p / (jt * 32);
        int rem = p % (jt * 32);
        int j = rem / 32;
        int ln = rem % 32;
        int col = j * 8 + (ln >> 2);
        int k0 = ks * 16 + (ln & 3) * 2;
        float v0 = __ldg(&Wg[k0 * fout + col]);
        float v1 = __ldg(&Wg[(k0 + 1) * fout + col]);
        float v2 = __ldg(&Wg[(k0 + 8) * fout + col]);
        float v3 = __ldg(&Wg[(k0 + 9) * fout + col]);
        __nv_bfloat16 h0 = __float2bfloat16_rn(v0);
        __nv_bfloat16 h1 = __float2bfloat16_rn(v1);
        __nv_bfloat16 h2 = __float2bfloat16_rn(v2);
        __nv_bfloat16 h3 = __float2bfloat16_rn(v3);
        unsigned bh0 = pack_bf16(v0, v1);
        unsigned bh1 = pack_bf16(v2, v3);
        unsigned bl0 = pack_bf16(v0 - __bfloat162float(h0), v1 - __bfloat162float(h1));
        unsigned bl1 = pack_bf16(v2 - __bfloat162float(h2), v3 - __bfloat162float(h3));
        out[p] = make_uint4(bh0, bh1, bl0, bl1);
    }
}

// ---------------- z0 = (noise + temb + label) * dinv --------------------------
__global__ void k_z0(const float* __restrict__ noise,
                     const float* __restrict__ lemb,
                     const float* __restrict__ temb,
                     const int* __restrict__ flag,
                     const int* __restrict__ deg,
                     float* __restrict__ z) {
    int idx = blockIdx.x * blockDim.x + threadIdx.x;
    if (idx >= NN * (DD / 4)) return;
    int node = idx >> 4;
    int f4 = idx & 15;
    float4 v = ((const float4*)noise)[idx];
    float4 tb = ((const float4*)temb)[f4];
    v.x += tb.x; v.y += tb.y; v.z += tb.z; v.w += tb.w;
    int fl = flag[node];
    if (fl == 1) {
        float4 l = ((const float4*)(lemb + DD))[f4];
        v.x += l.x; v.y += l.y; v.z += l.z; v.w += l.w;
    } else if (fl == 2) {
        float4 l = ((const float4*)lemb)[f4];
        v.x += l.x; v.y += l.y; v.z += l.z; v.w += l.w;
    }
    float di = rsqrtf((float)deg[node] + 1.0f);
    v.x *= di; v.y *= di; v.z *= di; v.w *= di;
    ((float4*)z)[idx] = v;
}

// ---------------- CSR build --------------------------------------------------
__global__ void k_scan1(const int* __restrict__ deg, int* off, int* bsum) {
    __shared__ int sh[SB];
    int i = blockIdx.x * SB + threadIdx.x;
    int v = (i < NN) ? deg[i] : 0;
    sh[threadIdx.x] = v;
    __syncthreads();
    for (int s = 1; s < SB; s <<= 1) {
        int t = (threadIdx.x >= s) ? sh[threadIdx.x - s] : 0;
        __syncthreads();
        sh[threadIdx.x] += t;
        __syncthreads();
    }
    if (i < NN) off[i] = sh[threadIdx.x] - v;
    if (threadIdx.x == SB - 1) bsum[blockIdx.x] = sh[SB - 1];
}

__global__ void k_scan2(int* bsum) {
    if (threadIdx.x == 0) {
        int acc = 0;
        for (int b = 0; b < NB; b++) { int t = bsum[b]; bsum[b] = acc; acc += t; }
    }
}

__global__ void k_scan3(int* off, const int* __restrict__ bsum) {
    int i = blockIdx.x * blockDim.x + threadIdx.x;
    if (i < NN) off[i] += bsum[i / SB];
    if (i == 0) off[NN] = EE;
}

__global__ void k_fill(const int* __restrict__ src, const int* __restrict__ dst,
                       const int* __restrict__ off, int* cur, int* csr) {
    int e = blockIdx.x * blockDim.x + threadIdx.x;
    if (e < EE) {
        int d = dst[e];
        int p = off[d] + atomicAdd(&cur[d], 1);
        csr[p] = src[e];
    }
}

// ---------------- 3x bf16-split MMA GEMM, software-pipelined ------------------
// EPI 0: Y = acc * dinv ; EPI 1: Y = silu(acc + bias)
// CONCAT: logical X = [X | X2] along K (FIN=256).
template <int FIN, int FOUT, int EPI, bool CONCAT>
__global__ void __launch_bounds__(256) k_mma(const float* __restrict__ X,
                                             const float* __restrict__ X2,
                                             const unsigned* __restrict__ WfG,
                                             float* __restrict__ Y,
                                             const int* __restrict__ deg,
                                             const float* __restrict__ bias) {
    constexpr int BM = (FOUT == 128) ? 64 : 128;
    constexpr int BK = (FIN == 64) ? 64 : 32;
    constexpr int NCHUNK = FIN / BK;
    constexpr bool DB = (NCHUNK > 1);
    constexpr int XROW = BK + 4;            // BK/2 hi words + BK/2 lo words + pad
    constexpr int NJ = 4;
    constexpr int NWX = FOUT / 32;
    constexpr int NLD = BM * (BK / 4) / 256;   // float4 loads per thread (=4)
    constexpr int SRCF = CONCAT ? 128 : FIN;   // row length of each source
    __shared__ unsigned Xs[(DB ? 2 : 1) * BM * XROW];

    int tid = threadIdx.x;
    int lane = tid & 31, wid = tid >> 5;
    int wx = wid % NWX;
    int wy = wid / NWX;
    int base = blockIdx.x * BM;

    float acc[2][NJ][4];
    #pragma unroll
    for (int mi = 0; mi < 2; mi++)
        #pragma unroll
        for (int j = 0; j < NJ; j++)
            #pragma unroll
            for (int q = 0; q < 4; q++) acc[mi][j][q] = 0.f;

    const uint4* Wf4 = (const uint4*)WfG;

    float4 pf[NLD];
    // ---- prefetch chunk 0 ----
    #pragma unroll
    for (int i = 0; i < NLD; i++) {
        int q = tid + i * 256;
        int r = q / (BK / 4), qq = q % (BK / 4);
        int gr = base + r; if (gr >= NN) gr = NN - 1;
        pf[i] = *(const float4*)&X[(size_t)gr * SRCF + qq * 4];
    }

    for (int c = 0; c < NCHUNK; c++) {
        // store prefetched chunk c into buffer c%2
        unsigned* buf = Xs + (DB ? (c & 1) * BM * XROW : 0);
        #pragma unroll
        for (int i = 0; i < NLD; i++) {
            int q = tid + i * 256;
            int r = q / (BK / 4), qq = q % (BK / 4);
            float4 v = pf[i];
            __nv_bfloat16 h0 = __float2bfloat16_rn(v.x);
            __nv_bfloat16 h1 = __float2bfloat16_rn(v.y);
            __nv_bfloat16 h2 = __float2bfloat16_rn(v.z);
            __nv_bfloat16 h3 = __float2bfloat16_rn(v.w);
            unsigned* row = buf + r * XROW;
            row[qq * 2]              = pack_bf16(v.x, v.y);
            row[qq * 2 + 1]          = pack_bf16(v.z, v.w);
            row[BK / 2 + qq * 2]     = pack_bf16(v.x - __bfloat162float(h0),
                                                 v.y - __bfloat162float(h1));
            row[BK / 2 + qq * 2 + 1] = pack_bf16(v.z - __bfloat162float(h2),
                                                 v.w - __bfloat162float(h3));
        }
        __syncthreads();
        // prefetch chunk c+1 (overlaps with compute below)
        if (c + 1 < NCHUNK) {
            int kbase = (c + 1) * BK;
            const float* Xp = (CONCAT && kbase >= 128) ? X2 : X;
            int ko = (CONCAT && kbase >= 128) ? kbase - 128 : kbase;
            #pragma unroll
            for (int i = 0; i < NLD; i++) {
                int q = tid + i * 256;
                int r = q / (BK / 4), qq = q % (BK / 4);
                int gr = base + r; if (gr >= NN) gr = NN - 1;
                pf[i] = *(const float4*)&Xp[(size_t)gr * SRCF + ko + qq * 4];
            }
        }
        // compute chunk c
        int kc = c * BK;
        #pragma unroll
        for (int kl = 0; kl < BK; kl += 16) {
            int ksg = (kc + kl) >> 4;
            unsigned ah[2][4], al[2][4];
            #pragma unroll
            for (int mi = 0; mi < 2; mi++) {
                int r = wy * 32 + mi * 16 + (lane >> 2);
                int kp = (kl >> 1) + (lane & 3);
                const unsigned* rp0 = buf + r * XROW;
                const unsigned* rp1 = buf + (r + 8) * XROW;
                ah[mi][0] = rp0[kp];      ah[mi][1] = rp1[kp];
                ah[mi][2] = rp0[kp + 4];  ah[mi][3] = rp1[kp + 4];
                al[mi][0] = rp0[kp + BK / 2];     al[mi][1] = rp1[kp + BK / 2];
                al[mi][2] = rp0[kp + BK / 2 + 4]; al[mi][3] = rp1[kp + BK / 2 + 4];
            }
            #pragma unroll
            for (int j = 0; j < NJ; j++) {
                uint4 b = __ldg(&Wf4[(ksg * (FOUT / 8) + wx * NJ + j) * 32 + lane]);
                #pragma unroll
                for (int mi = 0; mi < 2; mi++) {
                    mma16(acc[mi][j], al[mi], b.x, b.y);
                    mma16(acc[mi][j], ah[mi], b.z, b.w);
                    mma16(acc[mi][j], ah[mi], b.x, b.y);
                }
            }
        }
        if (c + 1 < NCHUNK) __syncthreads();
    }

    int cb = wx * 32 + 2 * (lane & 3);
    #pragma unroll
    for (int mi = 0; mi < 2; mi++) {
        int r0 = base + wy * 32 + mi * 16 + (lane >> 2);
        int r1 = r0 + 8;
        float s0 = 0.f, s1 = 0.f;
        if (EPI == 0) {
            s0 = (r0 < NN) ? rsqrtf((float)deg[r0] + 1.0f) : 0.f;
            s1 = (r1 < NN) ? rsqrtf((float)deg[r1] + 1.0f) : 0.f;
        }
        #pragma unroll
        for (int j = 0; j < NJ; j++) {
            int c = cb + j * 8;
            float bx = 0.f, by = 0.f;
            if (EPI == 1) { bx = __ldg(&bias[c]); by = __ldg(&bias[c + 1]); }
            if (r0 < NN) {
                float2* yp = (float2*)&Y[(size_t)r0 * FOUT + c];
                float2 o;
                if (EPI == 0) {
                    o = make_float2(acc[mi][j][0] * s0, acc[mi][j][1] * s0);
                } else {
                    float v0 = acc[mi][j][0] + bx;
                    float v1 = acc[mi][j][1] + by;
                    o = make_float2(v0 / (1.0f + expf(-v0)), v1 / (1.0f + expf(-v1)));
                }
                *yp = o;
            }
            if (r1 < NN) {
                float2* yp = (float2*)&Y[(size_t)r1 * FOUT + c];
                float2 o;
                if (EPI == 0) {
                    o = make_float2(acc[mi][j][2] * s1, acc[mi][j][3] * s1);
                } else {
                    float v2 = acc[mi][j][2] + bx;
                    float v3 = acc[mi][j][3] + by;
                    o = make_float2(v2 / (1.0f + expf(-v2)), v3 / (1.0f + expf(-v3)));
                }
                *yp = o;
            }
        }
    }
}

// ---------------- 64-wide gather ----------------------------------------------
// MODE 0: out = dinv*(sum z[src] + z[i])
// MODE 1: out = silu(dinv*(sum y[src] + y[i]) + b)
// MODE 2: out = silu(dinv*(sum y[src] + y[i]) + b) * dinv
template <int MODE>
__global__ void __launch_bounds__(256) k_gather64(const float* __restrict__ y,
                                                  const int* __restrict__ off,
                                                  const int* __restrict__ csr,
                                                  const int* __restrict__ deg,
                                                  const float* __restrict__ b,
                                                  float* __restrict__ out) {
    int warp = (blockIdx.x * 256 + threadIdx.x) >> 5;
    int lane = threadIdx.x & 31;
    if (warp >= NN) return;
    int beg = off[warp], end = off[warp + 1];
    float a0, a1;
    {
        float2 t = *(const float2*)(y + (size_t)warp * DD + lane * 2);
        a0 = t.x; a1 = t.y;
    }
    for (int eb = beg; eb < end; eb += 32) {
        int n = end - eb; if (n > 32) n = 32;
        int s = (lane < n) ? __ldg(&csr[eb + lane]) : 0;
        int j = 0;
        for (; j + 4 <= n; j += 4) {
            int s0 = __shfl_sync(0xffffffffu, s, j);
            int s1 = __shfl_sync(0xffffffffu, s, j + 1);
            int s2 = __shfl_sync(0xffffffffu, s, j + 2);
            int s3 = __shfl_sync(0xffffffffu, s, j + 3);
            float2 t0 = *(const float2*)(y + (size_t)s0 * DD + lane * 2);
            float2 t1 = *(const float2*)(y + (size_t)s1 * DD + lane * 2);
            float2 t2 = *(const float2*)(y + (size_t)s2 * DD + lane * 2);
            float2 t3 = *(const float2*)(y + (size_t)s3 * DD + lane * 2);
            a0 += (t0.x + t1.x) + (t2.x + t3.x);
            a1 += (t0.y + t1.y) + (t2.y + t3.y);
        }
        for (; j < n; j++) {
            int sj = __shfl_sync(0xffffffffu, s, j);
            float2 t = *(const float2*)(y + (size_t)sj * DD + lane * 2);
            a0 += t.x; a1 += t.y;
        }
    }
    float di = rsqrtf((float)deg[warp] + 1.0f);
    float o0, o1;
    if (MODE == 0) {
        o0 = di * a0; o1 = di * a1;
    } else {
        float v0 = di * a0 + b[lane * 2];
        float v1 = di * a1 + b[lane * 2 + 1];
        o0 = v0 / (1.0f + expf(-v0));
        o1 = v1 / (1.0f + expf(-v1));
        if (MODE == 2) { o0 *= di; o1 *= di; }
    }
    *(float2*)(out + (size_t)warp * DD + lane * 2) = make_float2(o0, o1);
}

// ---------------- launch ----------------------------------------------------
extern "C" void kernel_launch(void* const* d_in, const int* in_sizes, int n_in,
                              void* d_out, int out_size) {
    const float* noise_x   = (const float*)d_in[0];
    const int*   edge      = (const int*)d_in[1];
    const int*   t_in      = (const int*)d_in[2];
    const int*   train_anm = (const int*)d_in[3];
    const int*   train_nrm = (const int*)d_in[4];
    const float* time_w1   = (const float*)d_in[5];
    const float* time_b1   = (const float*)d_in[6];
    const float* time_w2   = (const float*)d_in[7];
    const float* time_b2   = (const float*)d_in[8];
    const float* label_emb = (const float*)d_in[9];
    const float* w0 = (const float*)d_in[10];
    const float* b0 = (const float*)d_in[11];
    const float* w1 = (const float*)d_in[12];
    const float* b1 = (const float*)d_in[13];
    const float* w2 = (const float*)d_in[14];
    const float* b2 = (const float*)d_in[15];
    const float* w3 = (const float*)d_in[16];
    const float* b3 = (const float*)d_in[17];
    float* out = (float*)d_out;

    const int* src = edge;
    const int* dst = edge + EE;
    int n_anm = in_sizes[3];
    int n_nrm = in_sizes[4];
    int n_fl = (n_anm > n_nrm) ? n_anm : n_nrm;

    float *p_temb, *p_ab, *p_h0, *p_h2;
    int *p_deg, *p_flag, *p_off, *p_bsum, *p_cur, *p_csr;
    unsigned *p_wf;
    cudaGetSymbolAddress((void**)&p_temb, g_temb);
    cudaGetSymbolAddress((void**)&p_ab,   g_ab);
    cudaGetSymbolAddress((void**)&p_h0,   g_h0);
    cudaGetSymbolAddress((void**)&p_h2,   g_h2);
    cudaGetSymbolAddress((void**)&p_deg,  g_deg);
    cudaGetSymbolAddress((void**)&p_flag, g_flag);
    cudaGetSymbolAddress((void**)&p_off,  g_off);
    cudaGetSymbolAddress((void**)&p_bsum, g_bsum);
    cudaGetSymbolAddress((void**)&p_cur,  g_cur);
    cudaGetSymbolAddress((void**)&p_csr,  g_csr);
    cudaGetSymbolAddress((void**)&p_wf,   g_wf);

    float* A = p_ab;                 // N x 64
    float* B = p_ab + (size_t)NN * DD;

    const int TB = 256;
    const int GB64  = (NN + 63) / 64;      // FOUT=128 tiles (BM=64)
    const int GB128 = (NN + 127) / 128;    // FOUT=64 tiles (BM=128)
    const int GGATH = (NN * 32 + TB - 1) / TB;

    k_init<<<(NN + TB - 1) / TB, TB>>>(p_deg, p_flag, p_cur);
    k_deg<<<(EE + TB - 1) / TB, TB>>>(dst, p_deg);
    k_wprep<<<6 + (n_fl + 255) / 256, 256>>>(w0, w1, w2, w3, p_wf,
                        t_in, time_w1, time_b1, time_w2, time_b2, p_temb,
                        train_anm, n_anm, train_nrm, n_nrm, p_flag);
    k_z0<<<(NN * 16 + TB - 1) / TB, TB>>>(noise_x, label_emb, p_temb, p_flag, p_deg, A);

    // ---- CSR build ----
    k_scan1<<<NB, SB>>>(p_deg, p_off, p_bsum);
    k_scan2<<<1, 32>>>(p_bsum);
    k_scan3<<<(NN + TB - 1) / TB, TB>>>(p_off, p_bsum);
    k_fill<<<(EE + TB - 1) / TB, TB>>>(src, dst, p_off, p_cur, p_csr);

    // ---- layer 0: aggregate-before ----
    k_gather64<0><<<GGATH, TB>>>(A, p_off, p_csr, p_deg, 0, B);
    k_mma<64, 128, 1, false><<<GB64, 256>>>(B, 0, p_wf + 0 * WFW, p_h0, p_deg, b0);

    // ---- layer 1: aggregate-after ----
    k_mma<128, 64, 0, false><<<GB128, 256>>>(p_h0, 0, p_wf + 1 * WFW, A, p_deg, 0);
    k_gather64<2><<<GGATH, TB>>>(A, p_off, p_csr, p_deg, b1, B);

    // ---- layer 2: aggregate-before ----
    k_gather64<0><<<GGATH, TB>>>(B, p_off, p_csr, p_deg, 0, A);
    k_mma<64, 128, 1, false><<<GB64, 256>>>(A, 0, p_wf + 2 * WFW, p_h2, p_deg, b2);

    // ---- layer 3: merged concat(h2,h0) GEMM, aggregate-after ----
    k_mma<256, 64, 0, true><<<GB128, 256>>>(p_h2, p_h0, p_wf + 3 * WFW, B, p_deg, 0);
    k_gather64<1><<<GGATH, TB>>>(B, p_off, p_csr, p_deg, b3, out);
}